// round 13
// baseline (speedup 1.0000x reference)
#include <cuda_runtime.h>
#include <cuda_bf16.h>
#include <cstdint>
#include <math.h>
#include <math_constants.h>

// ===========================================================================
// RecurrenceAttention — bf16 mma.sync; multi-stage cp.async GEMMs;
// persistent-column scores kernel writing P = exp(S) + fused Z partials;
// coalesced V store + fused transpose-scale kernel.
//
//  cvt_bf16   : Wq/Wkv/Wfc -> bf16 once
//  concat_h   : h = [mem ; x] bf16
//  fill_pos   : B2 pos half ; zero_a2row
//  G0         : q = x@Wq^T   -> A2 bf16 (q+u | shifted q+v)
//  G1         : kv = h@Wkv^T -> B2 k-half + Vr[bz][j][d] (coalesced)
//  g2_scores  : P = exp(mask(S)*0.125) bf16 + Zp partials
//  zinv       : RZ = 1/sum_y Zp
//  vtrans     : Vt[bz][d][j] = Vr[bz][j][d] * RZ[bz][j]  (SMEM transpose)
//  G3         : out = P @ Vt^T (pure bf16, masked K-chunks skipped)
//  G4         : y = of@Wfc^T + x + bfc  (fp32 out)
//  ln_kernel  : LayerNorm -> d_out
// ===========================================================================

// ---------------- scratch ----------------
__device__ __nv_bfloat16 g_h   [4096 * 1024];
__device__ __nv_bfloat16 g_Wqb [1024 * 1024];
__device__ __nv_bfloat16 g_Wkvb[2048 * 1024];
__device__ __nv_bfloat16 g_Wfcb[1024 * 1024];
__device__ __nv_bfloat16 g_A2  [32 * 1024 * 128];
__device__ __nv_bfloat16 g_B2  [32 * 2048 * 128];
__device__ __nv_bfloat16 g_Vr  [32 * 2048 * 64];       // [bz][j][d] row-major
__device__ __nv_bfloat16 g_V   [32 * 64 * 2048];       // Vt [bz][d][j]
__device__ __nv_bfloat16 g_S   [32u * 1024u * 2048u];  // holds P = exp(S)
__device__ float g_Zp [8 * 32 * 2048];
__device__ float g_RZ [32 * 2048];
__device__ __nv_bfloat16 g_of  [2048 * 1024];
__device__ float g_y [2048 * 1024];

// ---------------- helpers ----------------
__device__ __forceinline__ uint32_t smem_u32(const void* p) {
    uint32_t a;
    asm("{ .reg .u64 t; cvta.to.shared.u64 t, %1; cvt.u32.u64 %0, t; }"
        : "=r"(a) : "l"(p));
    return a;
}
__device__ __forceinline__ uint32_t pack_bf2(float a, float b) {
    __nv_bfloat162 h = __float22bfloat162_rn(make_float2(a, b));
    return *reinterpret_cast<uint32_t*>(&h);
}
__device__ __forceinline__ void ldsm4(uint32_t* r, uint32_t addr) {
    asm volatile("ldmatrix.sync.aligned.m8n8.x4.shared.b16 {%0,%1,%2,%3}, [%4];"
                 : "=r"(r[0]), "=r"(r[1]), "=r"(r[2]), "=r"(r[3]) : "r"(addr));
}
__device__ __forceinline__ void mma16(float* c, const uint32_t* a,
                                      uint32_t b0, uint32_t b1) {
    asm volatile(
        "mma.sync.aligned.m16n8k16.row.col.f32.bf16.bf16.f32 "
        "{%0,%1,%2,%3}, {%4,%5,%6,%7}, {%8,%9}, {%0,%1,%2,%3};"
        : "+f"(c[0]), "+f"(c[1]), "+f"(c[2]), "+f"(c[3])
        : "r"(a[0]), "r"(a[1]), "r"(a[2]), "r"(a[3]), "r"(b0), "r"(b1));
}
#define CP_ASYNC16(smem, gptr) \
    asm volatile("cp.async.cg.shared.global [%0], [%1], 16;" \
                 :: "r"(smem), "l"(gptr))
#define CP_COMMIT() asm volatile("cp.async.commit_group;" ::: "memory")
template <int N>
__device__ __forceinline__ void cp_wait() {
    asm volatile("cp.async.wait_group %0;" :: "n"(N) : "memory");
}

// fast exp on FMA pipe
__device__ __forceinline__ float fexp(float x) {
    float y = fmaxf(x * 1.4426950408889634f, -126.0f);
    float fn = floorf(y);
    float f  = y - fn;
    float p  = 1.5403530e-4f;
    p = fmaf(p, f, 1.3333558e-3f);
    p = fmaf(p, f, 9.6181291e-3f);
    p = fmaf(p, f, 5.5504109e-2f);
    p = fmaf(p, f, 2.4022651e-1f);
    p = fmaf(p, f, 6.9314718e-1f);
    p = fmaf(p, f, 1.0f);
    return p * __int_as_float(((int)fn + 127) << 23);
}

// ---------------- small kernels ----------------
__global__ __launch_bounds__(256) void cvt_bf16(const float* __restrict__ src,
                                                __nv_bfloat16* __restrict__ dst) {
    size_t i = (size_t)blockIdx.x * 256 + threadIdx.x;
    float4 v = reinterpret_cast<const float4*>(src)[i];
    uint2 o;
    o.x = pack_bf2(v.x, v.y);
    o.y = pack_bf2(v.z, v.w);
    *reinterpret_cast<uint2*>(dst + i * 4) = o;
}

__global__ __launch_bounds__(256) void concat_h(const float* __restrict__ x,
                                                const float* __restrict__ mem) {
    size_t idx = (size_t)blockIdx.x * 256 + threadIdx.x;
    size_t r   = idx >> 8;
    int    c4  = (int)(idx & 255);
    int beta = (int)(r >> 11);
    int s    = (int)(r & 2047);
    const float* src = (s < 1024)
        ? mem + ((size_t)(beta * 1024 + s)) * 1024
        : x   + ((size_t)(beta * 1024 + s - 1024)) * 1024;
    float4 v = reinterpret_cast<const float4*>(src)[c4];
    uint2 o;
    o.x = pack_bf2(v.x, v.y);
    o.y = pack_bf2(v.z, v.w);
    *reinterpret_cast<uint2*>(g_h + idx * 4) = o;
}

__global__ __launch_bounds__(256) void fill_pos(const float* __restrict__ pos_emb) {
    int idx = blockIdx.x * 256 + threadIdx.x;
    int d4 = idx & 15;
    int j  = (idx >> 4) & 2047;
    int bz = idx >> 15;
    int hh = bz & 15;
    float4 p = *reinterpret_cast<const float4*>(pos_emb + (size_t)j * 1024 + hh * 64 + d4 * 4);
    uint2 o;
    o.x = pack_bf2(p.x, p.y);
    o.y = pack_bf2(p.z, p.w);
    *reinterpret_cast<uint2*>(g_B2 + (((size_t)bz * 2048 + j) * 128) + 64 + d4 * 4) = o;
}

__global__ __launch_bounds__(256) void zero_a2row() {
    int t = blockIdx.x * 256 + threadIdx.x;
    int hh = t >> 6, d = t & 63;
    g_A2[(((size_t)hh) * 1024 + 1023) * 128 + 64 + d] = __float2bfloat16(0.0f);
}

// ---------------------------------------------------------------------------
// bf16 GEMM, NSTAGE-stage cp.async pipeline (prefetch distance NSTAGE-1).
// D(M x N) = A(M x K) * B(N x K)^T, bf16 K-major. BM=128, BN=128/64, BK=32.
// 256 threads, 8 warps 4x2, warp tile 32 x BN/2. 80B-padded rows.
// MODE: 0=qproj(A rows remapped in g_h)  1=kvproj  3=P@V  4=fc
// ---------------------------------------------------------------------------
template <int MODE, int BN, int NSTAGE, int OCC>
__global__ __launch_bounds__(256, OCC)
void gemm_bf16(const __nv_bfloat16* __restrict__ Ag,
               const __nv_bfloat16* __restrict__ Bg, int K,
               size_t batchA, size_t batchB,
               const float* __restrict__ aux0, const float* __restrict__ aux1,
               void* __restrict__ D0v, void* __restrict__ D1v) {
    constexpr int WN    = BN / 2;
    constexpr int NT    = WN / 8;
    constexpr int NG    = WN / 16;
    constexpr int BPASS = BN / 64;
    constexpr int LOG2BN = (BN == 64) ? 6 : 7;
    constexpr int STAGE  = (128 + BN) * 80;     // bytes per stage (A then B)
    constexpr int DIST   = NSTAGE - 1;

    extern __shared__ __align__(16) uint8_t dsm[];

    const int t    = threadIdx.x;
    const int wid  = t >> 5;
    const int lane = t & 31;
    const int wm   = wid >> 1;
    const int wn   = wid & 1;
    const int group = lane >> 2;
    const int tid4  = lane & 3;
    const int rowBase = blockIdx.y * 128;
    const int colBase = blockIdx.x * BN;

    const __nv_bfloat16* A = Ag + (size_t)blockIdx.z * batchA;
    const __nv_bfloat16* B = Bg + (size_t)blockIdx.z * batchB;

    int nch = K >> 5;
    if (MODE == 3) {
        int lim = ((rowBase + 1151) >> 5) + 1;   // skip fully-masked K-chunks
        if (lim < nch) nch = lim;
    }

    float acc[2][NT][4];
#pragma unroll
    for (int mt = 0; mt < 2; mt++)
#pragma unroll
        for (int nt = 0; nt < NT; nt++)
#pragma unroll
            for (int e = 0; e < 4; e++) acc[mt][nt][e] = 0.0f;

    const uint32_t dS = smem_u32(dsm);

    auto issue = [&](int ch) {
        const int kg0 = ch << 5;
        const uint32_t base = dS + (ch % NSTAGE) * STAGE;
#pragma unroll
        for (int p = 0; p < 2; p++) {
            int idx = p * 256 + t;
            int r = idx & 127, c = idx >> 7;
            int gr = rowBase + r;
            size_t arow = (MODE == 0)
                ? (size_t)(gr + 1024 + ((gr >> 10) << 10))   // x rows inside g_h
                : (size_t)gr;
            CP_ASYNC16(base + r * 80 + c * 16, A + arow * K + kg0 + c * 8);
        }
#pragma unroll
        for (int p = 0; p < BPASS; p++) {
            int idx = p * 256 + t;
            int r = idx & (BN - 1), c = idx >> LOG2BN;
            CP_ASYNC16(base + 128 * 80 + r * 80 + c * 16,
                       B + (size_t)(colBase + r) * K + kg0 + c * 8);
        }
        CP_COMMIT();
    };

    for (int s = 0; s < DIST && s < nch; s++) issue(s);

    const int lrow = (lane & 15) * 80;
    const int kh   = ((lane >> 4) & 1) * 16;

    for (int ch = 0; ch < nch; ch++) {
        if (ch + DIST < nch) issue(ch + DIST);

        int lag = nch - ch - 1;
        if (DIST == 3) {
            if (lag >= 3)      cp_wait<3>();
            else if (lag == 2) cp_wait<2>();
            else if (lag == 1) cp_wait<1>();
            else               cp_wait<0>();
        } else {
            if (lag >= 2)      cp_wait<2>();
            else if (lag == 1) cp_wait<1>();
            else               cp_wait<0>();
        }
        __syncthreads();

        const uint32_t aBase = dS + (ch % NSTAGE) * STAGE;
        const uint32_t bBase = aBase + 128 * 80;
#pragma unroll
        for (int ks = 0; ks < 2; ks++) {
            const int kb = ks * 32 + kh;
            uint32_t a[2][4];
#pragma unroll
            for (int mt = 0; mt < 2; mt++)
                ldsm4(a[mt], aBase + (wm * 32 + mt * 16) * 80 + lrow + kb);
            uint32_t bfr[NG][4];
#pragma unroll
            for (int g = 0; g < NG; g++)
                ldsm4(bfr[g], bBase + (wn * WN + g * 16) * 80 + lrow + kb);
#pragma unroll
            for (int mt = 0; mt < 2; mt++)
#pragma unroll
                for (int g = 0; g < NG; g++) {
                    mma16(acc[mt][2 * g],     a[mt], bfr[g][0], bfr[g][2]);
                    mma16(acc[mt][2 * g + 1], a[mt], bfr[g][1], bfr[g][3]);
                }
        }
        __syncthreads();
    }

    // ---- epilogue ----
    auto emit = [&](int gr, int gc, float v0, float v1) {
        if (MODE == 0) {
            __nv_bfloat16* A2p = (__nv_bfloat16*)D0v;
            float2 u2 = *reinterpret_cast<const float2*>(aux0 + gc);
            float2 w2 = *reinterpret_cast<const float2*>(aux1 + gc);
            int betaB = gr >> 10, iq = gr & 1023;
            int hh = gc >> 6, d = gc & 63;
            size_t base = ((size_t)(betaB * 16 + hh) * 1024 + iq) * 128 + d;
            uint32_t q  = pack_bf2(v0 + u2.x, v1 + u2.y);
            uint32_t pv = pack_bf2(v0 + w2.x, v1 + w2.y);
            *reinterpret_cast<uint32_t*>(A2p + base) = q;
            if (betaB == 1)
                *reinterpret_cast<uint32_t*>(A2p + base + 64) = pv;
            else if (iq >= 1)
                *reinterpret_cast<uint32_t*>(A2p + base - 64) = pv;
        } else if (MODE == 1) {
            int betaB = gr >> 11, jj = gr & 2047;
            if (gc < 1024) {
                __nv_bfloat16* B2p = (__nv_bfloat16*)D0v;
                int hh = gc >> 6, d = gc & 63;
                *reinterpret_cast<uint32_t*>(
                    B2p + ((size_t)(betaB * 16 + hh) * 2048 + jj) * 128 + d) =
                    pack_bf2(v0, v1);
            } else {
                // coalesced V store: Vr[bz][j][d]
                __nv_bfloat16* Vrp = (__nv_bfloat16*)D1v;
                int c = gc - 1024;
                int hh = c >> 6, d = c & 63;
                *reinterpret_cast<uint32_t*>(
                    Vrp + ((size_t)(betaB * 16 + hh) * 2048 + jj) * 64 + d) =
                    pack_bf2(v0, v1);
            }
        } else if (MODE == 3) {
            __nv_bfloat16* Op = (__nv_bfloat16*)D0v;
            int bz = blockIdx.z, beta = bz >> 4, hh = bz & 15;
            *reinterpret_cast<uint32_t*>(
                Op + ((size_t)(beta * 1024 + gr)) * 1024 + hh * 64 + gc) =
                pack_bf2(v0, v1);
        } else {
            float* Yp = (float*)D0v;
            float2 xv = *reinterpret_cast<const float2*>(aux0 + (size_t)gr * 1024 + gc);
            float2 bv = *reinterpret_cast<const float2*>(aux1 + gc);
            *reinterpret_cast<float2*>(Yp + (size_t)gr * 1024 + gc) =
                make_float2(v0 + xv.x + bv.x, v1 + xv.y + bv.y);
        }
    };

#pragma unroll
    for (int mt = 0; mt < 2; mt++) {
#pragma unroll
        for (int nt = 0; nt < NT; nt++) {
            int gr0 = rowBase + wm * 32 + mt * 16 + group;
            int gc  = colBase + wn * WN + nt * 8 + tid4 * 2;
            emit(gr0,     gc, acc[mt][nt][0], acc[mt][nt][1]);
            emit(gr0 + 8, gc, acc[mt][nt][2], acc[mt][nt][3]);
        }
    }
}

// ---------------------------------------------------------------------------
// Persistent-column scores kernel with a 4-stage cp.async B ring over the
// flattened (tile, chunk) stream. Writes P = exp(mask(S)*0.125) bf16 and
// column Z partials. grid (8 rowblocks, 32 bz).
// ---------------------------------------------------------------------------
__global__ __launch_bounds__(256, 2)
void g2_scores(const __nv_bfloat16* __restrict__ A2g,
               const __nv_bfloat16* __restrict__ B2g,
               __nv_bfloat16* __restrict__ Sp, float* __restrict__ Zp) {
    extern __shared__ __align__(16) uint8_t dsm[];
    uint8_t* sA  = dsm;                       // 4 chunks x 128 x 80 = 40960
    uint8_t* sB  = dsm + 40960;               // 4-stage ring x 10240 = 40960
    float*   sZw = (float*)(dsm + 81920);     // 4 x 128 floats

    const int t    = threadIdx.x;
    const int wid  = t >> 5;
    const int lane = t & 31;
    const int wm   = wid >> 1;
    const int wn   = wid & 1;
    const int group = lane >> 2;
    const int tid4  = lane & 3;
    const int y  = blockIdx.x;
    const int z  = blockIdx.y;
    const int rowBase = y * 128;

    const __nv_bfloat16* A = A2g + (size_t)z * 1024 * 128;
    const __nv_bfloat16* B = B2g + (size_t)z * 2048 * 128;
    float* Zrow = Zp + ((size_t)(y * 32) + z) * 2048;

#pragma unroll
    for (int ck = 0; ck < 4; ck++)
#pragma unroll
        for (int p = 0; p < 2; p++) {
            int idx = p * 256 + t;
            int r = idx & 127, c = idx >> 7;
            *reinterpret_cast<uint4*>(&sA[ck * 10240 + r * 80 + c * 16]) =
                *reinterpret_cast<const uint4*>(
                    A + (size_t)(rowBase + r) * 128 + ck * 32 + c * 8);
        }

    const int nvt = min(16, y + 9);
    const int totalc = nvt * 4;
    const int lrow = (lane & 15) * 80;
    const int kh   = ((lane >> 4) & 1) * 16;
    const uint32_t aS = smem_u32(sA);
    const uint32_t bS = smem_u32(sB);

    auto issueB = [&](int fc) {
        const __nv_bfloat16* Bt = B + (size_t)(fc >> 2) * 16384 + (fc & 3) * 32;
        const uint32_t base = bS + (fc & 3) * 10240;
#pragma unroll
        for (int p = 0; p < 2; p++) {
            int idx = p * 256 + t;
            int r = idx & 127, c = idx >> 7;
            CP_ASYNC16(base + r * 80 + c * 16, Bt + (size_t)r * 128 + c * 8);
        }
        CP_COMMIT();
    };

    for (int s = 0; s < 3 && s < totalc; s++) issueB(s);
    __syncthreads();

    int fc = 0;
    for (int ct = 0; ct < nvt; ct++) {
        float acc[2][8][4];
#pragma unroll
        for (int mt = 0; mt < 2; mt++)
#pragma unroll
            for (int nt = 0; nt < 8; nt++)
#pragma unroll
                for (int e = 0; e < 4; e++) acc[mt][nt][e] = 0.0f;

#pragma unroll
        for (int ck = 0; ck < 4; ck++, fc++) {
            if (fc + 3 < totalc) issueB(fc + 3);

            int lag = totalc - fc - 1;
            if (lag >= 3)      cp_wait<3>();
            else if (lag == 2) cp_wait<2>();
            else if (lag == 1) cp_wait<1>();
            else               cp_wait<0>();
            __syncthreads();

            uint32_t aBase = aS + ck * 10240;
            uint32_t bBase = bS + (fc & 3) * 10240;
#pragma unroll
            for (int ks = 0; ks < 2; ks++) {
                const int kb = ks * 32 + kh;
                uint32_t a[2][4];
#pragma unroll
                for (int mt = 0; mt < 2; mt++)
                    ldsm4(a[mt], aBase + (wm * 32 + mt * 16) * 80 + lrow + kb);
                uint32_t bfr[4][4];
#pragma unroll
                for (int g = 0; g < 4; g++)
                    ldsm4(bfr[g], bBase + (wn * 64 + g * 16) * 80 + lrow + kb);
#pragma unroll
                for (int mt = 0; mt < 2; mt++)
#pragma unroll
                    for (int g = 0; g < 4; g++) {
                        mma16(acc[mt][2 * g],     a[mt], bfr[g][0], bfr[g][2]);
                        mma16(acc[mt][2 * g + 1], a[mt], bfr[g][1], bfr[g][3]);
                    }
            }
            __syncthreads();
        }

        const int colBase = ct * 128;
        float colsum[8][2];
#pragma unroll
        for (int nt = 0; nt < 8; nt++) { colsum[nt][0] = 0.0f; colsum[nt][1] = 0.0f; }

#pragma unroll
        for (int mt = 0; mt < 2; mt++) {
#pragma unroll
            for (int nt = 0; nt < 8; nt++) {
                int gr0 = rowBase + wm * 32 + mt * 16 + group;
                int gc  = colBase + wn * 64 + nt * 8 + tid4 * 2;
                int gr1 = gr0 + 8;
                float e0 = (gc + 0 > gr0 + 1024) ? 0.0f : fexp(acc[mt][nt][0] * 0.125f);
                float e1 = (gc + 1 > gr0 + 1024) ? 0.0f : fexp(acc[mt][nt][1] * 0.125f);
                float e2 = (gc + 0 > gr1 + 1024) ? 0.0f : fexp(acc[mt][nt][2] * 0.125f);
                float e3 = (gc + 1 > gr1 + 1024) ? 0.0f : fexp(acc[mt][nt][3] * 0.125f);
                uint32_t pk0 = pack_bf2(e0, e1);
                uint32_t pk1 = pack_bf2(e2, e3);
                *reinterpret_cast<uint32_t*>(
                    Sp + ((size_t)z * 1024 + gr0) * 2048 + gc) = pk0;
                *reinterpret_cast<uint32_t*>(
                    Sp + ((size_t)z * 1024 + gr1) * 2048 + gc) = pk1;
                float2 f0 = __bfloat1622float2(*reinterpret_cast<__nv_bfloat162*>(&pk0));
                float2 f1 = __bfloat1622float2(*reinterpret_cast<__nv_bfloat162*>(&pk1));
                colsum[nt][0] += f0.x + f1.x;
                colsum[nt][1] += f0.y + f1.y;
            }
        }

#pragma unroll
        for (int nt = 0; nt < 8; nt++)
#pragma unroll
            for (int e = 0; e < 2; e++) {
                float v = colsum[nt][e];
                v += __shfl_xor_sync(0xFFFFFFFFu, v, 4);
                v += __shfl_xor_sync(0xFFFFFFFFu, v, 8);
                v += __shfl_xor_sync(0xFFFFFFFFu, v, 16);
                if (lane < 4)
                    sZw[wm * 128 + wn * 64 + nt * 8 + lane * 2 + e] = v;
            }
        __syncthreads();
        if (t < 128) {
            float zs = sZw[t] + sZw[128 + t] + sZw[256 + t] + sZw[384 + t];
            Zrow[colBase + t] = zs;
        }
        __syncthreads();
    }

    for (int ct = nvt; ct < 16; ct++)
        if (t < 128) Zrow[ct * 128 + t] = 0.0f;
}

// RZ[bz][j] = 1 / sum_y Zp[y][bz][j]
__global__ __launch_bounds__(256) void zinv() {
    int idx = blockIdx.x * 256 + threadIdx.x;
    int bz = idx >> 11, j = idx & 2047;
    float s = 0.0f;
#pragma unroll
    for (int y = 0; y < 8; y++)
        s += g_Zp[((size_t)(y * 32) + bz) * 2048 + j];
    g_RZ[bz * 2048 + j] = 1.0f / s;
}

// ---------------------------------------------------------------------------
// vtrans: Vt[bz][d][j] = Vr[bz][j][d] * RZ[bz][j]. SMEM-tiled transpose.
// grid (8 j-blocks of 256, 32 bz), 256 threads. 4 subtiles of 64j x 64d.
// ---------------------------------------------------------------------------
__global__ __launch_bounds__(256) void vtrans() {
    __shared__ __nv_bfloat16 sm[64][72];
    const int t  = threadIdx.x;
    const int jb = blockIdx.x;      // j-block (256 j)
    const int bz = blockIdx.y;

    const __nv_bfloat16* Vr = g_Vr + (size_t)bz * 2048 * 64;
    __nv_bfloat16* Vt = g_V + (size_t)bz * 64 * 2048;
    const float* RZ = g_RZ + bz * 2048;

    for (int sub = 0; sub < 4; sub++) {
        const int jbase = jb * 256 + sub * 64;
        // load: 64 j-rows x 64 d, coalesced uint4 (8 bf16)
        {
            int jr = t >> 2;           // 0..63
            int cq = t & 3;            // 0..3
#pragma unroll
            for (int p = 0; p < 2; p++) {
                int c8 = cq * 2 + p;   // 0..7
                uint4 o = *reinterpret_cast<const uint4*>(
                    Vr + (size_t)(jbase + jr) * 64 + c8 * 8);
                const __nv_bfloat16* e = reinterpret_cast<const __nv_bfloat16*>(&o);
#pragma unroll
                for (int k = 0; k < 8; k++)
                    sm[c8 * 8 + k][jr] = e[k];
            }
        }
        __syncthreads();
        // write: rows of d, j contiguous, scaled by RZ[j]
        {
            int d  = t >> 2;           // 0..63
            int jq = t & 3;            // 0..3
#pragma unroll
            for (int p = 0; p < 2; p++) {
                int j8 = jq * 16 + p * 8;
                uint4 o = *reinterpret_cast<const uint4*>(&sm[d][j8]);
                float4 r0 = *reinterpret_cast<const float4*>(RZ + jbase + j8);
                float4 r1 = *reinterpret_cast<const float4*>(RZ + jbase + j8 + 4);
                __nv_bfloat162* hp = reinterpret_cast<__nv_bfloat162*>(&o);
                float2 p0 = __bfloat1622float2(hp[0]);
                float2 p1 = __bfloat1622float2(hp[1]);
                float2 p2 = __bfloat1622float2(hp[2]);
                float2 p3 = __bfloat1622float2(hp[3]);
                o.x = pack_bf2(p0.x * r0.x, p0.y * r0.y);
                o.y = pack_bf2(p1.x * r0.z, p1.y * r0.w);
                o.z = pack_bf2(p2.x * r1.x, p2.y * r1.y);
                o.w = pack_bf2(p3.x * r1.z, p3.y * r1.w);
                *reinterpret_cast<uint4*>(Vt + (size_t)d * 2048 + jbase + j8) = o;
            }
        }
        __syncthreads();
    }
}

// ---------------------------------------------------------------------------
__global__ __launch_bounds__(256) void ln_kernel(const float* __restrict__ gamma,
                                                 const float* __restrict__ beta,
                                                 float* __restrict__ out) {
    int row = blockIdx.x;
    const float4* yr = reinterpret_cast<const float4*>(g_y + (size_t)row * 1024);
    int t = threadIdx.x;
    float4 v = yr[t];
    float s  = v.x + v.y + v.z + v.w;
    float s2 = v.x * v.x + v.y * v.y + v.z * v.z + v.w * v.w;
#pragma unroll
    for (int off = 16; off; off >>= 1) {
        s  += __shfl_xor_sync(0xFFFFFFFFu, s,  off);
        s2 += __shfl_xor_sync(0xFFFFFFFFu, s2, off);
    }
    __shared__ float shs[8], shs2[8];
    int w = t >> 5, lane = t & 31;
    if (lane == 0) { shs[w] = s; shs2[w] = s2; }
    __syncthreads();
    float ts = 0.0f, ts2 = 0.0f;
#pragma unroll
    for (int i = 0; i < 8; i++) { ts += shs[i]; ts2 += shs2[i]; }
    float mu   = ts * (1.0f / 1024.0f);
    float var  = ts2 * (1.0f / 1024.0f) - mu * mu;
    float rstd = rsqrtf(var + 1e-5f);

    float4 g = reinterpret_cast<const float4*>(gamma)[t];
    float4 b = reinterpret_cast<const float4*>(beta)[t];
    float4 o;
    o.x = (v.x - mu) * rstd * g.x + b.x;
    o.y = (v.y - mu) * rstd * g.y + b.y;
    o.z = (v.z - mu) * rstd * g.z + b.z;
    o.w = (v.w - mu) * rstd * g.w + b.w;
    reinterpret_cast<float4*>(out + (size_t)row * 1024)[t] = o;
}

// ---------------------------------------------------------------------------
extern "C" void kernel_launch(void* const* d_in, const int* in_sizes, int n_in,
                              void* d_out, int out_size) {
    const float* x    = (const float*)d_in[0];
    const float* pos  = (const float*)d_in[1];
    const float* u    = (const float*)d_in[2];
    const float* v    = (const float*)d_in[3];
    const float* mem  = (const float*)d_in[4];
    const float* Wq   = (const float*)d_in[6];
    const float* Wkv  = (const float*)d_in[7];
    const float* Wfc  = (const float*)d_in[8];
    const float* bfc  = (const float*)d_in[9];
    const float* gam  = (const float*)d_in[10];
    const float* bet  = (const float*)d_in[11];
    float* out = (float*)d_out;

    __nv_bfloat16 *A2, *B2, *Vt, *Vr, *h, *of, *Sp, *Wqb, *Wkvb, *Wfcb;
    float *y, *Zpp;
    cudaGetSymbolAddress((void**)&h,    g_h);
    cudaGetSymbolAddress((void**)&Wqb,  g_Wqb);
    cudaGetSymbolAddress((void**)&Wkvb, g_Wkvb);
    cudaGetSymbolAddress((void**)&Wfcb, g_Wfcb);
    cudaGetSymbolAddress((void**)&A2,   g_A2);
    cudaGetSymbolAddress((void**)&B2,   g_B2);
    cudaGetSymbolAddress((void**)&Vt,   g_V);
    cudaGetSymbolAddress((void**)&Vr,   g_Vr);
    cudaGetSymbolAddress((void**)&of,   g_of);
    cudaGetSymbolAddress((void**)&y,    g_y);
    cudaGetSymbolAddress((void**)&Sp,   g_S);
    cudaGetSymbolAddress((void**)&Zpp,  g_Zp);

    constexpr int SM64  = 4 * (128 + 64) * 80;    // 61440 (4-stage, BN=64)
    constexpr int SM128 = 3 * (128 + 128) * 80;   // 61440 (3-stage, BN=128)
    constexpr int SMG2  = 81920 + 2048;           // 83968
    static bool attr_done = false;
    if (!attr_done) {
        cudaFuncSetAttribute(g2_scores,
                             cudaFuncAttributeMaxDynamicSharedMemorySize, SMG2);
        cudaFuncSetAttribute(gemm_bf16<0, 64, 4, 2>,
                             cudaFuncAttributeMaxDynamicSharedMemorySize, SM64);
        cudaFuncSetAttribute(gemm_bf16<1, 128, 3, 3>,
                             cudaFuncAttributeMaxDynamicSharedMemorySize, SM128);
        cudaFuncSetAttribute(gemm_bf16<3, 64, 4, 2>,
                             cudaFuncAttributeMaxDynamicSharedMemorySize, SM64);
        cudaFuncSetAttribute(gemm_bf16<4, 64, 4, 2>,
                             cudaFuncAttributeMaxDynamicSharedMemorySize, SM64);
        attr_done = true;
    }

    cvt_bf16 <<<1024, 256>>>(Wq,  Wqb);
    cvt_bf16 <<<2048, 256>>>(Wkv, Wkvb);
    cvt_bf16 <<<1024, 256>>>(Wfc, Wfcb);
    concat_h <<<4096, 256>>>(x, mem);
    fill_pos <<<4096, 256>>>(pos);
    zero_a2row<<<4, 256>>>();

    // G0: q = x@Wq^T -> A2 (q+u | shifted q+v)
    gemm_bf16<0, 64, 4, 2><<<dim3(16, 16, 1), 256, SM64>>>(
        h, Wqb, 1024, 0, 0, u, v, A2, nullptr);
    // G1: kv = h@Wkv^T -> B2 k-half + Vr (coalesced), 3 CTAs/SM
    gemm_bf16<1, 128, 3, 3><<<dim3(16, 32, 1), 256, SM128>>>(
        h, Wkvb, 1024, 0, 0, nullptr, nullptr, B2, Vr);
    // G2: persistent-column scores -> P = exp(S) + fused Z partials
    g2_scores<<<dim3(8, 32), 256, SMG2>>>(A2, B2, Sp, Zpp);
    // RZ = 1 / sum_y Zp ; transpose + scale V
    zinv  <<<256, 256>>>();
    vtrans<<<dim3(8, 32), 256>>>();
    // G3: out = P @ Vt^T (pure bf16 GEMM)
    gemm_bf16<3, 64, 4, 2><<<dim3(1, 8, 32), 256, SM64>>>(
        Sp, Vt, 2048, (size_t)1024 * 2048, (size_t)64 * 2048,
        nullptr, nullptr, of, nullptr);
    // G4: y = of@Wfc^T + x + bfc
    gemm_bf16<4, 64, 4, 2><<<dim3(16, 16, 1), 256, SM64>>>(
        of, Wfcb, 1024, 0, 0, x, bfc, y, nullptr);
    // LayerNorm
    ln_kernel<<<2048, 256>>>(gam, bet, out);
}

// round 15
// speedup vs baseline: 1.1264x; 1.1264x over previous
#include <cuda_runtime.h>
#include <cuda_bf16.h>
#include <cstdint>
#include <math.h>
#include <math_constants.h>

// ===========================================================================
// RecurrenceAttention — bf16 mma.sync; 4-stage cp.async GEMMs; persistent-
// column scores kernel writing P = exp(S) + fused Z partials; coalesced V
// store + fused transpose-scale kernel (G1 pipeline identical to R12 winner).
//
//  cvt_bf16   : Wq/Wkv/Wfc -> bf16 once
//  concat_h   : h = [mem ; x] bf16
//  fill_pos   : B2 pos half ; zero_a2row
//  G0         : q = x@Wq^T   -> A2 bf16 (q+u | shifted q+v)
//  G1         : kv = h@Wkv^T -> B2 k-half + Vr[bz][j][d] (coalesced)
//  g2_scores  : P = exp(mask(S)*0.125) bf16 + Zp partials
//  zinv       : RZ = 1/sum_y Zp
//  vtrans     : Vt[bz][d][j] = Vr[bz][j][d] * RZ[bz][j]  (SMEM transpose)
//  G3         : out = P @ Vt^T (pure bf16, masked K-chunks skipped)
//  G4         : y = of@Wfc^T + x + bfc  (fp32 out)
//  ln_kernel  : LayerNorm -> d_out
// ===========================================================================

// ---------------- scratch ----------------
__device__ __nv_bfloat16 g_h   [4096 * 1024];
__device__ __nv_bfloat16 g_Wqb [1024 * 1024];
__device__ __nv_bfloat16 g_Wkvb[2048 * 1024];
__device__ __nv_bfloat16 g_Wfcb[1024 * 1024];
__device__ __nv_bfloat16 g_A2  [32 * 1024 * 128];
__device__ __nv_bfloat16 g_B2  [32 * 2048 * 128];
__device__ __nv_bfloat16 g_Vr  [32 * 2048 * 64];       // [bz][j][d] row-major
__device__ __nv_bfloat16 g_V   [32 * 64 * 2048];       // Vt [bz][d][j]
__device__ __nv_bfloat16 g_S   [32u * 1024u * 2048u];  // holds P = exp(S)
__device__ float g_Zp [8 * 32 * 2048];
__device__ float g_RZ [32 * 2048];
__device__ __nv_bfloat16 g_of  [2048 * 1024];
__device__ float g_y [2048 * 1024];

// ---------------- helpers ----------------
__device__ __forceinline__ uint32_t smem_u32(const void* p) {
    uint32_t a;
    asm("{ .reg .u64 t; cvta.to.shared.u64 t, %1; cvt.u32.u64 %0, t; }"
        : "=r"(a) : "l"(p));
    return a;
}
__device__ __forceinline__ uint32_t pack_bf2(float a, float b) {
    __nv_bfloat162 h = __float22bfloat162_rn(make_float2(a, b));
    return *reinterpret_cast<uint32_t*>(&h);
}
__device__ __forceinline__ void ldsm4(uint32_t* r, uint32_t addr) {
    asm volatile("ldmatrix.sync.aligned.m8n8.x4.shared.b16 {%0,%1,%2,%3}, [%4];"
                 : "=r"(r[0]), "=r"(r[1]), "=r"(r[2]), "=r"(r[3]) : "r"(addr));
}
__device__ __forceinline__ void mma16(float* c, const uint32_t* a,
                                      uint32_t b0, uint32_t b1) {
    asm volatile(
        "mma.sync.aligned.m16n8k16.row.col.f32.bf16.bf16.f32 "
        "{%0,%1,%2,%3}, {%4,%5,%6,%7}, {%8,%9}, {%0,%1,%2,%3};"
        : "+f"(c[0]), "+f"(c[1]), "+f"(c[2]), "+f"(c[3])
        : "r"(a[0]), "r"(a[1]), "r"(a[2]), "r"(a[3]), "r"(b0), "r"(b1));
}
#define CP_ASYNC16(smem, gptr) \
    asm volatile("cp.async.cg.shared.global [%0], [%1], 16;" \
                 :: "r"(smem), "l"(gptr))
#define CP_COMMIT() asm volatile("cp.async.commit_group;" ::: "memory")
template <int N>
__device__ __forceinline__ void cp_wait() {
    asm volatile("cp.async.wait_group %0;" :: "n"(N) : "memory");
}

// fast exp on FMA pipe
__device__ __forceinline__ float fexp(float x) {
    float y = fmaxf(x * 1.4426950408889634f, -126.0f);
    float fn = floorf(y);
    float f  = y - fn;
    float p  = 1.5403530e-4f;
    p = fmaf(p, f, 1.3333558e-3f);
    p = fmaf(p, f, 9.6181291e-3f);
    p = fmaf(p, f, 5.5504109e-2f);
    p = fmaf(p, f, 2.4022651e-1f);
    p = fmaf(p, f, 6.9314718e-1f);
    p = fmaf(p, f, 1.0f);
    return p * __int_as_float(((int)fn + 127) << 23);
}

// ---------------- small kernels ----------------
__global__ __launch_bounds__(256) void cvt_bf16(const float* __restrict__ src,
                                                __nv_bfloat16* __restrict__ dst) {
    size_t i = (size_t)blockIdx.x * 256 + threadIdx.x;
    float4 v = reinterpret_cast<const float4*>(src)[i];
    uint2 o;
    o.x = pack_bf2(v.x, v.y);
    o.y = pack_bf2(v.z, v.w);
    *reinterpret_cast<uint2*>(dst + i * 4) = o;
}

__global__ __launch_bounds__(256) void concat_h(const float* __restrict__ x,
                                                const float* __restrict__ mem) {
    size_t idx = (size_t)blockIdx.x * 256 + threadIdx.x;
    size_t r   = idx >> 8;
    int    c4  = (int)(idx & 255);
    int beta = (int)(r >> 11);
    int s    = (int)(r & 2047);
    const float* src = (s < 1024)
        ? mem + ((size_t)(beta * 1024 + s)) * 1024
        : x   + ((size_t)(beta * 1024 + s - 1024)) * 1024;
    float4 v = reinterpret_cast<const float4*>(src)[c4];
    uint2 o;
    o.x = pack_bf2(v.x, v.y);
    o.y = pack_bf2(v.z, v.w);
    *reinterpret_cast<uint2*>(g_h + idx * 4) = o;
}

__global__ __launch_bounds__(256) void fill_pos(const float* __restrict__ pos_emb) {
    int idx = blockIdx.x * 256 + threadIdx.x;
    int d4 = idx & 15;
    int j  = (idx >> 4) & 2047;
    int bz = idx >> 15;
    int hh = bz & 15;
    float4 p = *reinterpret_cast<const float4*>(pos_emb + (size_t)j * 1024 + hh * 64 + d4 * 4);
    uint2 o;
    o.x = pack_bf2(p.x, p.y);
    o.y = pack_bf2(p.z, p.w);
    *reinterpret_cast<uint2*>(g_B2 + (((size_t)bz * 2048 + j) * 128) + 64 + d4 * 4) = o;
}

__global__ __launch_bounds__(256) void zero_a2row() {
    int t = blockIdx.x * 256 + threadIdx.x;
    int hh = t >> 6, d = t & 63;
    g_A2[(((size_t)hh) * 1024 + 1023) * 128 + 64 + d] = __float2bfloat16(0.0f);
}

// ---------------------------------------------------------------------------
// bf16 GEMM, 4-stage cp.async pipeline (prefetch distance 3 chunks).
// D(M x N) = A(M x K) * B(N x K)^T, bf16 K-major. BM=128, BN=128/64, BK=32.
// 256 threads, 8 warps 4x2, warp tile 32 x BN/2. 80B-padded rows.
// MODE: 0=qproj(A rows remapped in g_h)  1=kvproj  3=P@V  4=fc
// ---------------------------------------------------------------------------
template <int MODE, int BN>
__global__ __launch_bounds__(256, 2)
void gemm_bf16(const __nv_bfloat16* __restrict__ Ag,
               const __nv_bfloat16* __restrict__ Bg, int K,
               size_t batchA, size_t batchB,
               const float* __restrict__ aux0, const float* __restrict__ aux1,
               void* __restrict__ D0v, void* __restrict__ D1v) {
    constexpr int WN    = BN / 2;
    constexpr int NT    = WN / 8;
    constexpr int NG    = WN / 16;
    constexpr int BPASS = BN / 64;
    constexpr int LOG2BN = (BN == 64) ? 6 : 7;
    constexpr int STAGE  = (128 + BN) * 80;     // bytes per stage (A then B)

    extern __shared__ __align__(16) uint8_t dsm[];

    const int t    = threadIdx.x;
    const int wid  = t >> 5;
    const int lane = t & 31;
    const int wm   = wid >> 1;
    const int wn   = wid & 1;
    const int group = lane >> 2;
    const int tid4  = lane & 3;
    const int rowBase = blockIdx.y * 128;
    const int colBase = blockIdx.x * BN;

    const __nv_bfloat16* A = Ag + (size_t)blockIdx.z * batchA;
    const __nv_bfloat16* B = Bg + (size_t)blockIdx.z * batchB;

    int nch = K >> 5;
    if (MODE == 3) {
        int lim = ((rowBase + 1151) >> 5) + 1;   // skip fully-masked K-chunks
        if (lim < nch) nch = lim;
    }

    float acc[2][NT][4];
#pragma unroll
    for (int mt = 0; mt < 2; mt++)
#pragma unroll
        for (int nt = 0; nt < NT; nt++)
#pragma unroll
            for (int e = 0; e < 4; e++) acc[mt][nt][e] = 0.0f;

    const uint32_t dS = smem_u32(dsm);

    auto issue = [&](int ch) {
        const int kg0 = ch << 5;
        const uint32_t base = dS + (ch & 3) * STAGE;
#pragma unroll
        for (int p = 0; p < 2; p++) {
            int idx = p * 256 + t;
            int r = idx & 127, c = idx >> 7;
            int gr = rowBase + r;
            size_t arow = (MODE == 0)
                ? (size_t)(gr + 1024 + ((gr >> 10) << 10))   // x rows inside g_h
                : (size_t)gr;
            CP_ASYNC16(base + r * 80 + c * 16, A + arow * K + kg0 + c * 8);
        }
#pragma unroll
        for (int p = 0; p < BPASS; p++) {
            int idx = p * 256 + t;
            int r = idx & (BN - 1), c = idx >> LOG2BN;
            CP_ASYNC16(base + 128 * 80 + r * 80 + c * 16,
                       B + (size_t)(colBase + r) * K + kg0 + c * 8);
        }
        CP_COMMIT();
    };

    for (int s = 0; s < 3 && s < nch; s++) issue(s);

    const int lrow = (lane & 15) * 80;
    const int kh   = ((lane >> 4) & 1) * 16;

    for (int ch = 0; ch < nch; ch++) {
        if (ch + 3 < nch) issue(ch + 3);

        int lag = nch - ch - 1;
        if (lag >= 3)      cp_wait<3>();
        else if (lag == 2) cp_wait<2>();
        else if (lag == 1) cp_wait<1>();
        else               cp_wait<0>();
        __syncthreads();

        const uint32_t aBase = dS + (ch & 3) * STAGE;
        const uint32_t bBase = aBase + 128 * 80;
#pragma unroll
        for (int ks = 0; ks < 2; ks++) {
            const int kb = ks * 32 + kh;
            uint32_t a[2][4];
#pragma unroll
            for (int mt = 0; mt < 2; mt++)
                ldsm4(a[mt], aBase + (wm * 32 + mt * 16) * 80 + lrow + kb);
            uint32_t bfr[NG][4];
#pragma unroll
            for (int g = 0; g < NG; g++)
                ldsm4(bfr[g], bBase + (wn * WN + g * 16) * 80 + lrow + kb);
#pragma unroll
            for (int mt = 0; mt < 2; mt++)
#pragma unroll
                for (int g = 0; g < NG; g++) {
                    mma16(acc[mt][2 * g],     a[mt], bfr[g][0], bfr[g][2]);
                    mma16(acc[mt][2 * g + 1], a[mt], bfr[g][1], bfr[g][3]);
                }
        }
        __syncthreads();
    }

    // ---- epilogue ----
    auto emit = [&](int gr, int gc, float v0, float v1) {
        if (MODE == 0) {
            __nv_bfloat16* A2p = (__nv_bfloat16*)D0v;
            float2 u2 = *reinterpret_cast<const float2*>(aux0 + gc);
            float2 w2 = *reinterpret_cast<const float2*>(aux1 + gc);
            int betaB = gr >> 10, iq = gr & 1023;
            int hh = gc >> 6, d = gc & 63;
            size_t base = ((size_t)(betaB * 16 + hh) * 1024 + iq) * 128 + d;
            uint32_t q  = pack_bf2(v0 + u2.x, v1 + u2.y);
            uint32_t pv = pack_bf2(v0 + w2.x, v1 + w2.y);
            *reinterpret_cast<uint32_t*>(A2p + base) = q;
            if (betaB == 1)
                *reinterpret_cast<uint32_t*>(A2p + base + 64) = pv;
            else if (iq >= 1)
                *reinterpret_cast<uint32_t*>(A2p + base - 64) = pv;
        } else if (MODE == 1) {
            int betaB = gr >> 11, jj = gr & 2047;
            if (gc < 1024) {
                __nv_bfloat16* B2p = (__nv_bfloat16*)D0v;
                int hh = gc >> 6, d = gc & 63;
                *reinterpret_cast<uint32_t*>(
                    B2p + ((size_t)(betaB * 16 + hh) * 2048 + jj) * 128 + d) =
                    pack_bf2(v0, v1);
            } else {
                // coalesced V store: Vr[bz][j][d]
                __nv_bfloat16* Vrp = (__nv_bfloat16*)D1v;
                int c = gc - 1024;
                int hh = c >> 6, d = c & 63;
                *reinterpret_cast<uint32_t*>(
                    Vrp + ((size_t)(betaB * 16 + hh) * 2048 + jj) * 64 + d) =
                    pack_bf2(v0, v1);
            }
        } else if (MODE == 3) {
            __nv_bfloat16* Op = (__nv_bfloat16*)D0v;
            int bz = blockIdx.z, beta = bz >> 4, hh = bz & 15;
            *reinterpret_cast<uint32_t*>(
                Op + ((size_t)(beta * 1024 + gr)) * 1024 + hh * 64 + gc) =
                pack_bf2(v0, v1);
        } else {
            float* Yp = (float*)D0v;
            float2 xv = *reinterpret_cast<const float2*>(aux0 + (size_t)gr * 1024 + gc);
            float2 bv = *reinterpret_cast<const float2*>(aux1 + gc);
            *reinterpret_cast<float2*>(Yp + (size_t)gr * 1024 + gc) =
                make_float2(v0 + xv.x + bv.x, v1 + xv.y + bv.y);
        }
    };

#pragma unroll
    for (int mt = 0; mt < 2; mt++) {
#pragma unroll
        for (int nt = 0; nt < NT; nt++) {
            int gr0 = rowBase + wm * 32 + mt * 16 + group;
            int gc  = colBase + wn * WN + nt * 8 + tid4 * 2;
            emit(gr0,     gc, acc[mt][nt][0], acc[mt][nt][1]);
            emit(gr0 + 8, gc, acc[mt][nt][2], acc[mt][nt][3]);
        }
    }
}

// ---------------------------------------------------------------------------
// Persistent-column scores kernel with a 4-stage cp.async B ring over the
// flattened (tile, chunk) stream. Writes P = exp(mask(S)*0.125) bf16 and
// column Z partials. grid (8 rowblocks, 32 bz).
// ---------------------------------------------------------------------------
__global__ __launch_bounds__(256, 2)
void g2_scores(const __nv_bfloat16* __restrict__ A2g,
               const __nv_bfloat16* __restrict__ B2g,
               __nv_bfloat16* __restrict__ Sp, float* __restrict__ Zp) {
    extern __shared__ __align__(16) uint8_t dsm[];
    uint8_t* sA  = dsm;                       // 4 chunks x 128 x 80 = 40960
    uint8_t* sB  = dsm + 40960;               // 4-stage ring x 10240 = 40960
    float*   sZw = (float*)(dsm + 81920);     // 4 x 128 floats

    const int t    = threadIdx.x;
    const int wid  = t >> 5;
    const int lane = t & 31;
    const int wm   = wid >> 1;
    const int wn   = wid & 1;
    const int group = lane >> 2;
    const int tid4  = lane & 3;
    const int y  = blockIdx.x;
    const int z  = blockIdx.y;
    const int rowBase = y * 128;

    const __nv_bfloat16* A = A2g + (size_t)z * 1024 * 128;
    const __nv_bfloat16* B = B2g + (size_t)z * 2048 * 128;
    float* Zrow = Zp + ((size_t)(y * 32) + z) * 2048;

#pragma unroll
    for (int ck = 0; ck < 4; ck++)
#pragma unroll
        for (int p = 0; p < 2; p++) {
            int idx = p * 256 + t;
            int r = idx & 127, c = idx >> 7;
            *reinterpret_cast<uint4*>(&sA[ck * 10240 + r * 80 + c * 16]) =
                *reinterpret_cast<const uint4*>(
                    A + (size_t)(rowBase + r) * 128 + ck * 32 + c * 8);
        }

    const int nvt = min(16, y + 9);
    const int totalc = nvt * 4;
    const int lrow = (lane & 15) * 80;
    const int kh   = ((lane >> 4) & 1) * 16;
    const uint32_t aS = smem_u32(sA);
    const uint32_t bS = smem_u32(sB);

    auto issueB = [&](int fc) {
        const __nv_bfloat16* Bt = B + (size_t)(fc >> 2) * 16384 + (fc & 3) * 32;
        const uint32_t base = bS + (fc & 3) * 10240;
#pragma unroll
        for (int p = 0; p < 2; p++) {
            int idx = p * 256 + t;
            int r = idx & 127, c = idx >> 7;
            CP_ASYNC16(base + r * 80 + c * 16, Bt + (size_t)r * 128 + c * 8);
        }
        CP_COMMIT();
    };

    for (int s = 0; s < 3 && s < totalc; s++) issueB(s);
    __syncthreads();

    int fc = 0;
    for (int ct = 0; ct < nvt; ct++) {
        float acc[2][8][4];
#pragma unroll
        for (int mt = 0; mt < 2; mt++)
#pragma unroll
            for (int nt = 0; nt < 8; nt++)
#pragma unroll
                for (int e = 0; e < 4; e++) acc[mt][nt][e] = 0.0f;

#pragma unroll
        for (int ck = 0; ck < 4; ck++, fc++) {
            if (fc + 3 < totalc) issueB(fc + 3);

            int lag = totalc - fc - 1;
            if (lag >= 3)      cp_wait<3>();
            else if (lag == 2) cp_wait<2>();
            else if (lag == 1) cp_wait<1>();
            else               cp_wait<0>();
            __syncthreads();

            uint32_t aBase = aS + ck * 10240;
            uint32_t bBase = bS + (fc & 3) * 10240;
#pragma unroll
            for (int ks = 0; ks < 2; ks++) {
                const int kb = ks * 32 + kh;
                uint32_t a[2][4];
#pragma unroll
                for (int mt = 0; mt < 2; mt++)
                    ldsm4(a[mt], aBase + (wm * 32 + mt * 16) * 80 + lrow + kb);
                uint32_t bfr[4][4];
#pragma unroll
                for (int g = 0; g < 4; g++)
                    ldsm4(bfr[g], bBase + (wn * 64 + g * 16) * 80 + lrow + kb);
#pragma unroll
                for (int mt = 0; mt < 2; mt++)
#pragma unroll
                    for (int g = 0; g < 4; g++) {
                        mma16(acc[mt][2 * g],     a[mt], bfr[g][0], bfr[g][2]);
                        mma16(acc[mt][2 * g + 1], a[mt], bfr[g][1], bfr[g][3]);
                    }
            }
            __syncthreads();
        }

        const int colBase = ct * 128;
        float colsum[8][2];
#pragma unroll
        for (int nt = 0; nt < 8; nt++) { colsum[nt][0] = 0.0f; colsum[nt][1] = 0.0f; }

#pragma unroll
        for (int mt = 0; mt < 2; mt++) {
#pragma unroll
            for (int nt = 0; nt < 8; nt++) {
                int gr0 = rowBase + wm * 32 + mt * 16 + group;
                int gc  = colBase + wn * 64 + nt * 8 + tid4 * 2;
                int gr1 = gr0 + 8;
                float e0 = (gc + 0 > gr0 + 1024) ? 0.0f : fexp(acc[mt][nt][0] * 0.125f);
                float e1 = (gc + 1 > gr0 + 1024) ? 0.0f : fexp(acc[mt][nt][1] * 0.125f);
                float e2 = (gc + 0 > gr1 + 1024) ? 0.0f : fexp(acc[mt][nt][2] * 0.125f);
                float e3 = (gc + 1 > gr1 + 1024) ? 0.0f : fexp(acc[mt][nt][3] * 0.125f);
                uint32_t pk0 = pack_bf2(e0, e1);
                uint32_t pk1 = pack_bf2(e2, e3);
                *reinterpret_cast<uint32_t*>(
                    Sp + ((size_t)z * 1024 + gr0) * 2048 + gc) = pk0;
                *reinterpret_cast<uint32_t*>(
                    Sp + ((size_t)z * 1024 + gr1) * 2048 + gc) = pk1;
                float2 f0 = __bfloat1622float2(*reinterpret_cast<__nv_bfloat162*>(&pk0));
                float2 f1 = __bfloat1622float2(*reinterpret_cast<__nv_bfloat162*>(&pk1));
                colsum[nt][0] += f0.x + f1.x;
                colsum[nt][1] += f0.y + f1.y;
            }
        }

#pragma unroll
        for (int nt = 0; nt < 8; nt++)
#pragma unroll
            for (int e = 0; e < 2; e++) {
                float v = colsum[nt][e];
                v += __shfl_xor_sync(0xFFFFFFFFu, v, 4);
                v += __shfl_xor_sync(0xFFFFFFFFu, v, 8);
                v += __shfl_xor_sync(0xFFFFFFFFu, v, 16);
                if (lane < 4)
                    sZw[wm * 128 + wn * 64 + nt * 8 + lane * 2 + e] = v;
            }
        __syncthreads();
        if (t < 128) {
            float zs = sZw[t] + sZw[128 + t] + sZw[256 + t] + sZw[384 + t];
            Zrow[colBase + t] = zs;
        }
        __syncthreads();
    }

    for (int ct = nvt; ct < 16; ct++)
        if (t < 128) Zrow[ct * 128 + t] = 0.0f;
}

// RZ[bz][j] = 1 / sum_y Zp[y][bz][j]
__global__ __launch_bounds__(256) void zinv() {
    int idx = blockIdx.x * 256 + threadIdx.x;
    int bz = idx >> 11, j = idx & 2047;
    float s = 0.0f;
#pragma unroll
    for (int y = 0; y < 8; y++)
        s += g_Zp[((size_t)(y * 32) + bz) * 2048 + j];
    g_RZ[bz * 2048 + j] = 1.0f / s;
}

// ---------------------------------------------------------------------------
// vtrans: Vt[bz][d][j] = Vr[bz][j][d] * RZ[bz][j]. SMEM-tiled transpose.
// grid (8 j-blocks of 256, 32 bz), 256 threads. 4 subtiles of 64j x 64d.
// ---------------------------------------------------------------------------
__global__ __launch_bounds__(256) void vtrans() {
    __shared__ __nv_bfloat16 sm[64][72];
    const int t  = threadIdx.x;
    const int jb = blockIdx.x;
    const int bz = blockIdx.y;

    const __nv_bfloat16* Vr = g_Vr + (size_t)bz * 2048 * 64;
    __nv_bfloat16* Vt = g_V + (size_t)bz * 64 * 2048;
    const float* RZ = g_RZ + bz * 2048;

    for (int sub = 0; sub < 4; sub++) {
        const int jbase = jb * 256 + sub * 64;
        {
            int jr = t >> 2;
            int cq = t & 3;
#pragma unroll
            for (int p = 0; p < 2; p++) {
                int c8 = cq * 2 + p;
                uint4 o = *reinterpret_cast<const uint4*>(
                    Vr + (size_t)(jbase + jr) * 64 + c8 * 8);
                const __nv_bfloat16* e = reinterpret_cast<const __nv_bfloat16*>(&o);
#pragma unroll
                for (int k = 0; k < 8; k++)
                    sm[c8 * 8 + k][jr] = e[k];
            }
        }
        __syncthreads();
        {
            int d  = t >> 2;
            int jq = t & 3;
#pragma unroll
            for (int p = 0; p < 2; p++) {
                int j8 = jq * 16 + p * 8;
                uint4 o = *reinterpret_cast<const uint4*>(&sm[d][j8]);
                float4 r0 = *reinterpret_cast<const float4*>(RZ + jbase + j8);
                float4 r1 = *reinterpret_cast<const float4*>(RZ + jbase + j8 + 4);
                __nv_bfloat162* hp = reinterpret_cast<__nv_bfloat162*>(&o);
                float2 p0 = __bfloat1622float2(hp[0]);
                float2 p1 = __bfloat1622float2(hp[1]);
                float2 p2 = __bfloat1622float2(hp[2]);
                float2 p3 = __bfloat1622float2(hp[3]);
                o.x = pack_bf2(p0.x * r0.x, p0.y * r0.y);
                o.y = pack_bf2(p1.x * r0.z, p1.y * r0.w);
                o.z = pack_bf2(p2.x * r1.x, p2.y * r1.y);
                o.w = pack_bf2(p3.x * r1.z, p3.y * r1.w);
                *reinterpret_cast<uint4*>(Vt + (size_t)d * 2048 + jbase + j8) = o;
            }
        }
        __syncthreads();
    }
}

// ---------------------------------------------------------------------------
__global__ __launch_bounds__(256) void ln_kernel(const float* __restrict__ gamma,
                                                 const float* __restrict__ beta,
                                                 float* __restrict__ out) {
    int row = blockIdx.x;
    const float4* yr = reinterpret_cast<const float4*>(g_y + (size_t)row * 1024);
    int t = threadIdx.x;
    float4 v = yr[t];
    float s  = v.x + v.y + v.z + v.w;
    float s2 = v.x * v.x + v.y * v.y + v.z * v.z + v.w * v.w;
#pragma unroll
    for (int off = 16; off; off >>= 1) {
        s  += __shfl_xor_sync(0xFFFFFFFFu, s,  off);
        s2 += __shfl_xor_sync(0xFFFFFFFFu, s2, off);
    }
    __shared__ float shs[8], shs2[8];
    int w = t >> 5, lane = t & 31;
    if (lane == 0) { shs[w] = s; shs2[w] = s2; }
    __syncthreads();
    float ts = 0.0f, ts2 = 0.0f;
#pragma unroll
    for (int i = 0; i < 8; i++) { ts += shs[i]; ts2 += shs2[i]; }
    float mu   = ts * (1.0f / 1024.0f);
    float var  = ts2 * (1.0f / 1024.0f) - mu * mu;
    float rstd = rsqrtf(var + 1e-5f);

    float4 g = reinterpret_cast<const float4*>(gamma)[t];
    float4 b = reinterpret_cast<const float4*>(beta)[t];
    float4 o;
    o.x = (v.x - mu) * rstd * g.x + b.x;
    o.y = (v.y - mu) * rstd * g.y + b.y;
    o.z = (v.z - mu) * rstd * g.z + b.z;
    o.w = (v.w - mu) * rstd * g.w + b.w;
    reinterpret_cast<float4*>(out + (size_t)row * 1024)[t] = o;
}

// ---------------------------------------------------------------------------
extern "C" void kernel_launch(void* const* d_in, const int* in_sizes, int n_in,
                              void* d_out, int out_size) {
    const float* x    = (const float*)d_in[0];
    const float* pos  = (const float*)d_in[1];
    const float* u    = (const float*)d_in[2];
    const float* v    = (const float*)d_in[3];
    const float* mem  = (const float*)d_in[4];
    const float* Wq   = (const float*)d_in[6];
    const float* Wkv  = (const float*)d_in[7];
    const float* Wfc  = (const float*)d_in[8];
    const float* bfc  = (const float*)d_in[9];
    const float* gam  = (const float*)d_in[10];
    const float* bet  = (const float*)d_in[11];
    float* out = (float*)d_out;

    __nv_bfloat16 *A2, *B2, *Vt, *Vr, *h, *of, *Sp, *Wqb, *Wkvb, *Wfcb;
    float *y, *Zpp;
    cudaGetSymbolAddress((void**)&h,    g_h);
    cudaGetSymbolAddress((void**)&Wqb,  g_Wqb);
    cudaGetSymbolAddress((void**)&Wkvb, g_Wkvb);
    cudaGetSymbolAddress((void**)&Wfcb, g_Wfcb);
    cudaGetSymbolAddress((void**)&A2,   g_A2);
    cudaGetSymbolAddress((void**)&B2,   g_B2);
    cudaGetSymbolAddress((void**)&Vt,   g_V);
    cudaGetSymbolAddress((void**)&Vr,   g_Vr);
    cudaGetSymbolAddress((void**)&of,   g_of);
    cudaGetSymbolAddress((void**)&y,    g_y);
    cudaGetSymbolAddress((void**)&Sp,   g_S);
    cudaGetSymbolAddress((void**)&Zpp,  g_Zp);

    constexpr int SM64  = 4 * (128 + 64) * 80;    // 61440
    constexpr int SM128 = 4 * (128 + 128) * 80;   // 81920
    constexpr int SMG2  = 81920 + 2048;           // 83968
    static bool attr_done = false;
    if (!attr_done) {
        cudaFuncSetAttribute(g2_scores,
                             cudaFuncAttributeMaxDynamicSharedMemorySize, SMG2);
        cudaFuncSetAttribute(gemm_bf16<0, 64>,
                             cudaFuncAttributeMaxDynamicSharedMemorySize, SM64);
        cudaFuncSetAttribute(gemm_bf16<1, 128>,
                             cudaFuncAttributeMaxDynamicSharedMemorySize, SM128);
        cudaFuncSetAttribute(gemm_bf16<3, 64>,
                             cudaFuncAttributeMaxDynamicSharedMemorySize, SM64);
        cudaFuncSetAttribute(gemm_bf16<4, 64>,
                             cudaFuncAttributeMaxDynamicSharedMemorySize, SM64);
        attr_done = true;
    }

    cvt_bf16 <<<1024, 256>>>(Wq,  Wqb);
    cvt_bf16 <<<2048, 256>>>(Wkv, Wkvb);
    cvt_bf16 <<<1024, 256>>>(Wfc, Wfcb);
    concat_h <<<4096, 256>>>(x, mem);
    fill_pos <<<4096, 256>>>(pos);
    zero_a2row<<<4, 256>>>();

    // G0: q = x@Wq^T -> A2 (q+u | shifted q+v)
    gemm_bf16<0, 64><<<dim3(16, 16, 1), 256, SM64>>>(
        h, Wqb, 1024, 0, 0, u, v, A2, nullptr);
    // G1: kv = h@Wkv^T -> B2 k-half + Vr (coalesced), R12 pipeline config
    gemm_bf16<1, 128><<<dim3(16, 32, 1), 256, SM128>>>(
        h, Wkvb, 1024, 0, 0, nullptr, nullptr, B2, Vr);
    // G2: persistent-column scores -> P = exp(S) + fused Z partials
    g2_scores<<<dim3(8, 32), 256, SMG2>>>(A2, B2, Sp, Zpp);
    // RZ = 1 / sum_y Zp ; transpose + scale V
    zinv  <<<256, 256>>>();
    vtrans<<<dim3(8, 32), 256>>>();
    // G3: out = P @ Vt^T (pure bf16 GEMM)
    gemm_bf16<3, 64><<<dim3(1, 8, 32), 256, SM64>>>(
        Sp, Vt, 2048, (size_t)1024 * 2048, (size_t)64 * 2048,
        nullptr, nullptr, of, nullptr);
    // G4: y = of@Wfc^T + x + bfc
    gemm_bf16<4, 64><<<dim3(16, 16, 1), 256, SM64>>>(
        of, Wfcb, 1024, 0, 0, x, bfc, y, nullptr);
    // LayerNorm
    ln_kernel<<<2048, 256>>>(gam, bet, out);
}

// round 16
// speedup vs baseline: 1.1366x; 1.0091x over previous
#include <cuda_runtime.h>
#include <cuda_bf16.h>
#include <cstdint>
#include <math.h>
#include <math_constants.h>

// ===========================================================================
// RecurrenceAttention — bf16 mma.sync; 4-stage cp.async GEMMs; persistent-
// column scores kernel (cp.async B-ring spanning tile boundaries) writing
// P = exp(S) + fused column-Z partials. R12 champion configuration.
//
//  cvt_bf16   : Wq/Wkv/Wfc -> bf16 once
//  concat_h   : h = [mem ; x] bf16
//  fill_pos   : B2 pos half ; zero_a2row
//  G0         : q = x@Wq^T   -> A2 bf16 (q+u | shifted q+v)
//  G1         : kv = h@Wkv^T -> B2 bf16 k-half + Vt bf16 ([bz][d][j])
//  g2_scores  : P = exp(mask(S)*0.125) bf16 + Zp partials
//  zinv/vscale: RZ = 1/sum Zp ; Vt *= RZ
//  G3         : out = P @ Vt^T (pure bf16, masked K-chunks skipped)
//  G4         : y = of@Wfc^T + x + bfc  (fp32 out)
//  ln_kernel  : LayerNorm -> d_out
// ===========================================================================

// ---------------- scratch ----------------
__device__ __nv_bfloat16 g_h   [4096 * 1024];
__device__ __nv_bfloat16 g_Wqb [1024 * 1024];
__device__ __nv_bfloat16 g_Wkvb[2048 * 1024];
__device__ __nv_bfloat16 g_Wfcb[1024 * 1024];
__device__ __nv_bfloat16 g_A2  [32 * 1024 * 128];
__device__ __nv_bfloat16 g_B2  [32 * 2048 * 128];
__device__ __nv_bfloat16 g_V   [32 * 64 * 2048];       // [bz][d][j]
__device__ __nv_bfloat16 g_S   [32u * 1024u * 2048u];  // holds P = exp(S)
__device__ float g_Zp [8 * 32 * 2048];
__device__ float g_RZ [32 * 2048];
__device__ __nv_bfloat16 g_of  [2048 * 1024];
__device__ float g_y [2048 * 1024];

// ---------------- helpers ----------------
__device__ __forceinline__ uint32_t smem_u32(const void* p) {
    uint32_t a;
    asm("{ .reg .u64 t; cvta.to.shared.u64 t, %1; cvt.u32.u64 %0, t; }"
        : "=r"(a) : "l"(p));
    return a;
}
__device__ __forceinline__ uint32_t pack_bf2(float a, float b) {
    __nv_bfloat162 h = __float22bfloat162_rn(make_float2(a, b));
    return *reinterpret_cast<uint32_t*>(&h);
}
__device__ __forceinline__ void ldsm4(uint32_t* r, uint32_t addr) {
    asm volatile("ldmatrix.sync.aligned.m8n8.x4.shared.b16 {%0,%1,%2,%3}, [%4];"
                 : "=r"(r[0]), "=r"(r[1]), "=r"(r[2]), "=r"(r[3]) : "r"(addr));
}
__device__ __forceinline__ void mma16(float* c, const uint32_t* a,
                                      uint32_t b0, uint32_t b1) {
    asm volatile(
        "mma.sync.aligned.m16n8k16.row.col.f32.bf16.bf16.f32 "
        "{%0,%1,%2,%3}, {%4,%5,%6,%7}, {%8,%9}, {%0,%1,%2,%3};"
        : "+f"(c[0]), "+f"(c[1]), "+f"(c[2]), "+f"(c[3])
        : "r"(a[0]), "r"(a[1]), "r"(a[2]), "r"(a[3]), "r"(b0), "r"(b1));
}
#define CP_ASYNC16(smem, gptr) \
    asm volatile("cp.async.cg.shared.global [%0], [%1], 16;" \
                 :: "r"(smem), "l"(gptr))
#define CP_COMMIT() asm volatile("cp.async.commit_group;" ::: "memory")
template <int N>
__device__ __forceinline__ void cp_wait() {
    asm volatile("cp.async.wait_group %0;" :: "n"(N) : "memory");
}

// fast exp on FMA pipe
__device__ __forceinline__ float fexp(float x) {
    float y = fmaxf(x * 1.4426950408889634f, -126.0f);
    float fn = floorf(y);
    float f  = y - fn;
    float p  = 1.5403530e-4f;
    p = fmaf(p, f, 1.3333558e-3f);
    p = fmaf(p, f, 9.6181291e-3f);
    p = fmaf(p, f, 5.5504109e-2f);
    p = fmaf(p, f, 2.4022651e-1f);
    p = fmaf(p, f, 6.9314718e-1f);
    p = fmaf(p, f, 1.0f);
    return p * __int_as_float(((int)fn + 127) << 23);
}

// ---------------- small kernels ----------------
__global__ __launch_bounds__(256) void cvt_bf16(const float* __restrict__ src,
                                                __nv_bfloat16* __restrict__ dst) {
    size_t i = (size_t)blockIdx.x * 256 + threadIdx.x;
    float4 v = reinterpret_cast<const float4*>(src)[i];
    uint2 o;
    o.x = pack_bf2(v.x, v.y);
    o.y = pack_bf2(v.z, v.w);
    *reinterpret_cast<uint2*>(dst + i * 4) = o;
}

__global__ __launch_bounds__(256) void concat_h(const float* __restrict__ x,
                                                const float* __restrict__ mem) {
    size_t idx = (size_t)blockIdx.x * 256 + threadIdx.x;
    size_t r   = idx >> 8;
    int    c4  = (int)(idx & 255);
    int beta = (int)(r >> 11);
    int s    = (int)(r & 2047);
    const float* src = (s < 1024)
        ? mem + ((size_t)(beta * 1024 + s)) * 1024
        : x   + ((size_t)(beta * 1024 + s - 1024)) * 1024;
    float4 v = reinterpret_cast<const float4*>(src)[c4];
    uint2 o;
    o.x = pack_bf2(v.x, v.y);
    o.y = pack_bf2(v.z, v.w);
    *reinterpret_cast<uint2*>(g_h + idx * 4) = o;
}

__global__ __launch_bounds__(256) void fill_pos(const float* __restrict__ pos_emb) {
    int idx = blockIdx.x * 256 + threadIdx.x;
    int d4 = idx & 15;
    int j  = (idx >> 4) & 2047;
    int bz = idx >> 15;
    int hh = bz & 15;
    float4 p = *reinterpret_cast<const float4*>(pos_emb + (size_t)j * 1024 + hh * 64 + d4 * 4);
    uint2 o;
    o.x = pack_bf2(p.x, p.y);
    o.y = pack_bf2(p.z, p.w);
    *reinterpret_cast<uint2*>(g_B2 + (((size_t)bz * 2048 + j) * 128) + 64 + d4 * 4) = o;
}

__global__ __launch_bounds__(256) void zero_a2row() {
    int t = blockIdx.x * 256 + threadIdx.x;
    int hh = t >> 6, d = t & 63;
    g_A2[(((size_t)hh) * 1024 + 1023) * 128 + 64 + d] = __float2bfloat16(0.0f);
}

// ---------------------------------------------------------------------------
// bf16 GEMM, 4-stage cp.async pipeline (prefetch distance 3 chunks).
// D(M x N) = A(M x K) * B(N x K)^T, bf16 K-major. BM=128, BN=128/64, BK=32.
// 256 threads, 8 warps 4x2, warp tile 32 x BN/2. 80B-padded rows.
// MODE: 0=qproj(A rows remapped in g_h)  1=kvproj  3=P@V  4=fc
// ---------------------------------------------------------------------------
template <int MODE, int BN>
__global__ __launch_bounds__(256, 2)
void gemm_bf16(const __nv_bfloat16* __restrict__ Ag,
               const __nv_bfloat16* __restrict__ Bg, int K,
               size_t batchA, size_t batchB,
               const float* __restrict__ aux0, const float* __restrict__ aux1,
               void* __restrict__ D0v, void* __restrict__ D1v) {
    constexpr int WN    = BN / 2;
    constexpr int NT    = WN / 8;
    constexpr int NG    = WN / 16;
    constexpr int BPASS = BN / 64;
    constexpr int LOG2BN = (BN == 64) ? 6 : 7;
    constexpr int STAGE  = (128 + BN) * 80;     // bytes per stage (A then B)

    extern __shared__ __align__(16) uint8_t dsm[];

    const int t    = threadIdx.x;
    const int wid  = t >> 5;
    const int lane = t & 31;
    const int wm   = wid >> 1;
    const int wn   = wid & 1;
    const int group = lane >> 2;
    const int tid4  = lane & 3;
    const int rowBase = blockIdx.y * 128;
    const int colBase = blockIdx.x * BN;

    const __nv_bfloat16* A = Ag + (size_t)blockIdx.z * batchA;
    const __nv_bfloat16* B = Bg + (size_t)blockIdx.z * batchB;

    int nch = K >> 5;
    if (MODE == 3) {
        int lim = ((rowBase + 1151) >> 5) + 1;   // skip fully-masked K-chunks
        if (lim < nch) nch = lim;
    }

    float acc[2][NT][4];
#pragma unroll
    for (int mt = 0; mt < 2; mt++)
#pragma unroll
        for (int nt = 0; nt < NT; nt++)
#pragma unroll
            for (int e = 0; e < 4; e++) acc[mt][nt][e] = 0.0f;

    const uint32_t dS = smem_u32(dsm);

    auto issue = [&](int ch) {
        const int kg0 = ch << 5;
        const uint32_t base = dS + (ch & 3) * STAGE;
#pragma unroll
        for (int p = 0; p < 2; p++) {
            int idx = p * 256 + t;
            int r = idx & 127, c = idx >> 7;
            int gr = rowBase + r;
            size_t arow = (MODE == 0)
                ? (size_t)(gr + 1024 + ((gr >> 10) << 10))   // x rows inside g_h
                : (size_t)gr;
            CP_ASYNC16(base + r * 80 + c * 16, A + arow * K + kg0 + c * 8);
        }
#pragma unroll
        for (int p = 0; p < BPASS; p++) {
            int idx = p * 256 + t;
            int r = idx & (BN - 1), c = idx >> LOG2BN;
            CP_ASYNC16(base + 128 * 80 + r * 80 + c * 16,
                       B + (size_t)(colBase + r) * K + kg0 + c * 8);
        }
        CP_COMMIT();
    };

    for (int s = 0; s < 3 && s < nch; s++) issue(s);

    const int lrow = (lane & 15) * 80;
    const int kh   = ((lane >> 4) & 1) * 16;

    for (int ch = 0; ch < nch; ch++) {
        if (ch + 3 < nch) issue(ch + 3);

        int lag = nch - ch - 1;
        if (lag >= 3)      cp_wait<3>();
        else if (lag == 2) cp_wait<2>();
        else if (lag == 1) cp_wait<1>();
        else               cp_wait<0>();
        __syncthreads();

        const uint32_t aBase = dS + (ch & 3) * STAGE;
        const uint32_t bBase = aBase + 128 * 80;
#pragma unroll
        for (int ks = 0; ks < 2; ks++) {
            const int kb = ks * 32 + kh;
            uint32_t a[2][4];
#pragma unroll
            for (int mt = 0; mt < 2; mt++)
                ldsm4(a[mt], aBase + (wm * 32 + mt * 16) * 80 + lrow + kb);
            uint32_t bfr[NG][4];
#pragma unroll
            for (int g = 0; g < NG; g++)
                ldsm4(bfr[g], bBase + (wn * WN + g * 16) * 80 + lrow + kb);
#pragma unroll
            for (int mt = 0; mt < 2; mt++)
#pragma unroll
                for (int g = 0; g < NG; g++) {
                    mma16(acc[mt][2 * g],     a[mt], bfr[g][0], bfr[g][2]);
                    mma16(acc[mt][2 * g + 1], a[mt], bfr[g][1], bfr[g][3]);
                }
        }
        __syncthreads();
    }

    // ---- epilogue ----
    auto emit = [&](int gr, int gc, float v0, float v1) {
        if (MODE == 0) {
            __nv_bfloat16* A2p = (__nv_bfloat16*)D0v;
            float2 u2 = *reinterpret_cast<const float2*>(aux0 + gc);
            float2 w2 = *reinterpret_cast<const float2*>(aux1 + gc);
            int betaB = gr >> 10, iq = gr & 1023;
            int hh = gc >> 6, d = gc & 63;
            size_t base = ((size_t)(betaB * 16 + hh) * 1024 + iq) * 128 + d;
            uint32_t q  = pack_bf2(v0 + u2.x, v1 + u2.y);
            uint32_t pv = pack_bf2(v0 + w2.x, v1 + w2.y);
            *reinterpret_cast<uint32_t*>(A2p + base) = q;
            if (betaB == 1)
                *reinterpret_cast<uint32_t*>(A2p + base + 64) = pv;
            else if (iq >= 1)
                *reinterpret_cast<uint32_t*>(A2p + base - 64) = pv;
        } else if (MODE == 1) {
            int betaB = gr >> 11, jj = gr & 2047;
            if (gc < 1024) {
                __nv_bfloat16* B2p = (__nv_bfloat16*)D0v;
                int hh = gc >> 6, d = gc & 63;
                *reinterpret_cast<uint32_t*>(
                    B2p + ((size_t)(betaB * 16 + hh) * 2048 + jj) * 128 + d) =
                    pack_bf2(v0, v1);
            } else {
                __nv_bfloat16* Vp = (__nv_bfloat16*)D1v;
                int c = gc - 1024;
                int hh = c >> 6, d = c & 63;
                size_t base = ((size_t)(betaB * 16 + hh) * 64 + d) * 2048 + jj;
                Vp[base]        = __float2bfloat16(v0);
                Vp[base + 2048] = __float2bfloat16(v1);
            }
        } else if (MODE == 3) {
            __nv_bfloat16* Op = (__nv_bfloat16*)D0v;
            int bz = blockIdx.z, beta = bz >> 4, hh = bz & 15;
            *reinterpret_cast<uint32_t*>(
                Op + ((size_t)(beta * 1024 + gr)) * 1024 + hh * 64 + gc) =
                pack_bf2(v0, v1);
        } else {
            float* Yp = (float*)D0v;
            float2 xv = *reinterpret_cast<const float2*>(aux0 + (size_t)gr * 1024 + gc);
            float2 bv = *reinterpret_cast<const float2*>(aux1 + gc);
            *reinterpret_cast<float2*>(Yp + (size_t)gr * 1024 + gc) =
                make_float2(v0 + xv.x + bv.x, v1 + xv.y + bv.y);
        }
    };

#pragma unroll
    for (int mt = 0; mt < 2; mt++) {
#pragma unroll
        for (int nt = 0; nt < NT; nt++) {
            int gr0 = rowBase + wm * 32 + mt * 16 + group;
            int gc  = colBase + wn * WN + nt * 8 + tid4 * 2;
            emit(gr0,     gc, acc[mt][nt][0], acc[mt][nt][1]);
            emit(gr0 + 8, gc, acc[mt][nt][2], acc[mt][nt][3]);
        }
    }
}

// ---------------------------------------------------------------------------
// Persistent-column scores kernel with a 4-stage cp.async B ring over the
// flattened (tile, chunk) stream. Writes P = exp(mask(S)*0.125) bf16 and
// column Z partials. grid (8 rowblocks, 32 bz).
// ---------------------------------------------------------------------------
__global__ __launch_bounds__(256, 2)
void g2_scores(const __nv_bfloat16* __restrict__ A2g,
               const __nv_bfloat16* __restrict__ B2g,
               __nv_bfloat16* __restrict__ Sp, float* __restrict__ Zp) {
    extern __shared__ __align__(16) uint8_t dsm[];
    uint8_t* sA  = dsm;                       // 4 chunks x 128 x 80 = 40960
    uint8_t* sB  = dsm + 40960;               // 4-stage ring x 10240 = 40960
    float*   sZw = (float*)(dsm + 81920);     // 4 x 128 floats

    const int t    = threadIdx.x;
    const int wid  = t >> 5;
    const int lane = t & 31;
    const int wm   = wid >> 1;
    const int wn   = wid & 1;
    const int group = lane >> 2;
    const int tid4  = lane & 3;
    const int y  = blockIdx.x;
    const int z  = blockIdx.y;
    const int rowBase = y * 128;

    const __nv_bfloat16* A = A2g + (size_t)z * 1024 * 128;
    const __nv_bfloat16* B = B2g + (size_t)z * 2048 * 128;
    __nv_bfloat16* Srow = Sp + (size_t)z * 1024 * 2048;
    float* Zrow = Zp + ((size_t)(y * 32) + z) * 2048;

#pragma unroll
    for (int ck = 0; ck < 4; ck++)
#pragma unroll
        for (int p = 0; p < 2; p++) {
            int idx = p * 256 + t;
            int r = idx & 127, c = idx >> 7;
            *reinterpret_cast<uint4*>(&sA[ck * 10240 + r * 80 + c * 16]) =
                *reinterpret_cast<const uint4*>(
                    A + (size_t)(rowBase + r) * 128 + ck * 32 + c * 8);
        }

    const int nvt = min(16, y + 9);
    const int totalc = nvt * 4;
    const int lrow = (lane & 15) * 80;
    const int kh   = ((lane >> 4) & 1) * 16;
    const uint32_t aS = smem_u32(sA);
    const uint32_t bS = smem_u32(sB);

    auto issueB = [&](int fc) {
        const __nv_bfloat16* Bt = B + (size_t)(fc >> 2) * 16384 + (fc & 3) * 32;
        const uint32_t base = bS + (fc & 3) * 10240;
#pragma unroll
        for (int p = 0; p < 2; p++) {
            int idx = p * 256 + t;
            int r = idx & 127, c = idx >> 7;
            CP_ASYNC16(base + r * 80 + c * 16, Bt + (size_t)r * 128 + c * 8);
        }
        CP_COMMIT();
    };

    for (int s = 0; s < 3 && s < totalc; s++) issueB(s);
    __syncthreads();

    int fc = 0;
    for (int ct = 0; ct < nvt; ct++) {
        float acc[2][8][4];
#pragma unroll
        for (int mt = 0; mt < 2; mt++)
#pragma unroll
            for (int nt = 0; nt < 8; nt++)
#pragma unroll
                for (int e = 0; e < 4; e++) acc[mt][nt][e] = 0.0f;

#pragma unroll
        for (int ck = 0; ck < 4; ck++, fc++) {
            if (fc + 3 < totalc) issueB(fc + 3);

            int lag = totalc - fc - 1;
            if (lag >= 3)      cp_wait<3>();
            else if (lag == 2) cp_wait<2>();
            else if (lag == 1) cp_wait<1>();
            else               cp_wait<0>();
            __syncthreads();

            uint32_t aBase = aS + ck * 10240;
            uint32_t bBase = bS + (fc & 3) * 10240;
#pragma unroll
            for (int ks = 0; ks < 2; ks++) {
                const int kb = ks * 32 + kh;
                uint32_t a[2][4];
#pragma unroll
                for (int mt = 0; mt < 2; mt++)
                    ldsm4(a[mt], aBase + (wm * 32 + mt * 16) * 80 + lrow + kb);
                uint32_t bfr[4][4];
#pragma unroll
                for (int g = 0; g < 4; g++)
                    ldsm4(bfr[g], bBase + (wn * 64 + g * 16) * 80 + lrow + kb);
#pragma unroll
                for (int mt = 0; mt < 2; mt++)
#pragma unroll
                    for (int g = 0; g < 4; g++) {
                        mma16(acc[mt][2 * g],     a[mt], bfr[g][0], bfr[g][2]);
                        mma16(acc[mt][2 * g + 1], a[mt], bfr[g][1], bfr[g][3]);
                    }
            }
            __syncthreads();
        }

        const int colBase = ct * 128;
        float colsum[8][2];
#pragma unroll
        for (int nt = 0; nt < 8; nt++) { colsum[nt][0] = 0.0f; colsum[nt][1] = 0.0f; }

#pragma unroll
        for (int mt = 0; mt < 2; mt++) {
#pragma unroll
            for (int nt = 0; nt < 8; nt++) {
                int gr0 = rowBase + wm * 32 + mt * 16 + group;
                int gc  = colBase + wn * 64 + nt * 8 + tid4 * 2;
                int gr1 = gr0 + 8;
                float e0 = (gc + 0 > gr0 + 1024) ? 0.0f : fexp(acc[mt][nt][0] * 0.125f);
                float e1 = (gc + 1 > gr0 + 1024) ? 0.0f : fexp(acc[mt][nt][1] * 0.125f);
                float e2 = (gc + 0 > gr1 + 1024) ? 0.0f : fexp(acc[mt][nt][2] * 0.125f);
                float e3 = (gc + 1 > gr1 + 1024) ? 0.0f : fexp(acc[mt][nt][3] * 0.125f);
                uint32_t pk0 = pack_bf2(e0, e1);
                uint32_t pk1 = pack_bf2(e2, e3);
                *reinterpret_cast<uint32_t*>(Srow + (size_t)gr0 * 2048 + gc) = pk0;
                *reinterpret_cast<uint32_t*>(Srow + (size_t)gr1 * 2048 + gc) = pk1;
                float2 f0 = __bfloat1622float2(*reinterpret_cast<__nv_bfloat162*>(&pk0));
                float2 f1 = __bfloat1622float2(*reinterpret_cast<__nv_bfloat162*>(&pk1));
                colsum[nt][0] += f0.x + f1.x;
                colsum[nt][1] += f0.y + f1.y;
            }
        }

#pragma unroll
        for (int nt = 0; nt < 8; nt++)
#pragma unroll
            for (int e = 0; e < 2; e++) {
                float v = colsum[nt][e];
                v += __shfl_xor_sync(0xFFFFFFFFu, v, 4);
                v += __shfl_xor_sync(0xFFFFFFFFu, v, 8);
                v += __shfl_xor_sync(0xFFFFFFFFu, v, 16);
                if (lane < 4)
                    sZw[wm * 128 + wn * 64 + nt * 8 + lane * 2 + e] = v;
            }
        __syncthreads();
        if (t < 128) {
            float zs = sZw[t] + sZw[128 + t] + sZw[256 + t] + sZw[384 + t];
            Zrow[colBase + t] = zs;
        }
        // NOTE: no trailing sync needed — the next sZw write is ordered
        // behind the next tile's chunk-loop __syncthreads().
    }

    for (int ct = nvt; ct < 16; ct++)
        if (t < 128) Zrow[ct * 128 + t] = 0.0f;
}

// RZ[bz][j] = 1 / sum_y Zp[y][bz][j]
__global__ __launch_bounds__(256) void zinv() {
    int idx = blockIdx.x * 256 + threadIdx.x;
    int bz = idx >> 11, j = idx & 2047;
    float s = 0.0f;
#pragma unroll
    for (int y = 0; y < 8; y++)
        s += g_Zp[((size_t)(y * 32) + bz) * 2048 + j];
    g_RZ[bz * 2048 + j] = 1.0f / s;
}

// Vt[bz][d][j] *= RZ[bz][j]  (8 bf16 per thread)
__global__ __launch_bounds__(256) void vscale() {
    int i = blockIdx.x * 256 + threadIdx.x;
    int j8 = (i & 255) * 8;
    int bz = i >> 14;
    __nv_bfloat16* vp = g_V + ((size_t)(i >> 8)) * 2048 + j8;
    const float* rz = g_RZ + bz * 2048 + j8;
    uint4 o = *reinterpret_cast<const uint4*>(vp);
    float4 r0 = *reinterpret_cast<const float4*>(rz);
    float4 r1 = *reinterpret_cast<const float4*>(rz + 4);
    __nv_bfloat162* hp = reinterpret_cast<__nv_bfloat162*>(&o);
    float2 p0 = __bfloat1622float2(hp[0]);
    float2 p1 = __bfloat1622float2(hp[1]);
    float2 p2 = __bfloat1622float2(hp[2]);
    float2 p3 = __bfloat1622float2(hp[3]);
    o.x = pack_bf2(p0.x * r0.x, p0.y * r0.y);
    o.y = pack_bf2(p1.x * r0.z, p1.y * r0.w);
    o.z = pack_bf2(p2.x * r1.x, p2.y * r1.y);
    o.w = pack_bf2(p3.x * r1.z, p3.y * r1.w);
    *reinterpret_cast<uint4*>(vp) = o;
}

// ---------------------------------------------------------------------------
__global__ __launch_bounds__(256) void ln_kernel(const float* __restrict__ gamma,
                                                 const float* __restrict__ beta,
                                                 float* __restrict__ out) {
    int row = blockIdx.x;
    const float4* yr = reinterpret_cast<const float4*>(g_y + (size_t)row * 1024);
    int t = threadIdx.x;
    float4 v = yr[t];
    float s  = v.x + v.y + v.z + v.w;
    float s2 = v.x * v.x + v.y * v.y + v.z * v.z + v.w * v.w;
#pragma unroll
    for (int off = 16; off; off >>= 1) {
        s  += __shfl_xor_sync(0xFFFFFFFFu, s,  off);
        s2 += __shfl_xor_sync(0xFFFFFFFFu, s2, off);
    }
    __shared__ float shs[8], shs2[8];
    int w = t >> 5, lane = t & 31;
    if (lane == 0) { shs[w] = s; shs2[w] = s2; }
    __syncthreads();
    float ts = 0.0f, ts2 = 0.0f;
#pragma unroll
    for (int i = 0; i < 8; i++) { ts += shs[i]; ts2 += shs2[i]; }
    float mu   = ts * (1.0f / 1024.0f);
    float var  = ts2 * (1.0f / 1024.0f) - mu * mu;
    float rstd = rsqrtf(var + 1e-5f);

    float4 g = reinterpret_cast<const float4*>(gamma)[t];
    float4 b = reinterpret_cast<const float4*>(beta)[t];
    float4 o;
    o.x = (v.x - mu) * rstd * g.x + b.x;
    o.y = (v.y - mu) * rstd * g.y + b.y;
    o.z = (v.z - mu) * rstd * g.z + b.z;
    o.w = (v.w - mu) * rstd * g.w + b.w;
    reinterpret_cast<float4*>(out + (size_t)row * 1024)[t] = o;
}

// ---------------------------------------------------------------------------
extern "C" void kernel_launch(void* const* d_in, const int* in_sizes, int n_in,
                              void* d_out, int out_size) {
    const float* x    = (const float*)d_in[0];
    const float* pos  = (const float*)d_in[1];
    const float* u    = (const float*)d_in[2];
    const float* v    = (const float*)d_in[3];
    const float* mem  = (const float*)d_in[4];
    const float* Wq   = (const float*)d_in[6];
    const float* Wkv  = (const float*)d_in[7];
    const float* Wfc  = (const float*)d_in[8];
    const float* bfc  = (const float*)d_in[9];
    const float* gam  = (const float*)d_in[10];
    const float* bet  = (const float*)d_in[11];
    float* out = (float*)d_out;

    __nv_bfloat16 *A2, *B2, *Vt, *h, *of, *Sp, *Wqb, *Wkvb, *Wfcb;
    float *y, *Zpp;
    cudaGetSymbolAddress((void**)&h,    g_h);
    cudaGetSymbolAddress((void**)&Wqb,  g_Wqb);
    cudaGetSymbolAddress((void**)&Wkvb, g_Wkvb);
    cudaGetSymbolAddress((void**)&Wfcb, g_Wfcb);
    cudaGetSymbolAddress((void**)&A2,   g_A2);
    cudaGetSymbolAddress((void**)&B2,   g_B2);
    cudaGetSymbolAddress((void**)&Vt,   g_V);
    cudaGetSymbolAddress((void**)&of,   g_of);
    cudaGetSymbolAddress((void**)&y,    g_y);
    cudaGetSymbolAddress((void**)&Sp,   g_S);
    cudaGetSymbolAddress((void**)&Zpp,  g_Zp);

    constexpr int SM64  = 4 * (128 + 64) * 80;    // 61440
    constexpr int SM128 = 4 * (128 + 128) * 80;   // 81920
    constexpr int SMG2  = 81920 + 2048;           // 83968
    static bool attr_done = false;
    if (!attr_done) {
        cudaFuncSetAttribute(g2_scores,
                             cudaFuncAttributeMaxDynamicSharedMemorySize, SMG2);
        cudaFuncSetAttribute(gemm_bf16<0, 64>,
                             cudaFuncAttributeMaxDynamicSharedMemorySize, SM64);
        cudaFuncSetAttribute(gemm_bf16<1, 128>,
                             cudaFuncAttributeMaxDynamicSharedMemorySize, SM128);
        cudaFuncSetAttribute(gemm_bf16<3, 64>,
                             cudaFuncAttributeMaxDynamicSharedMemorySize, SM64);
        cudaFuncSetAttribute(gemm_bf16<4, 64>,
                             cudaFuncAttributeMaxDynamicSharedMemorySize, SM64);
        attr_done = true;
    }

    cvt_bf16 <<<1024, 256>>>(Wq,  Wqb);
    cvt_bf16 <<<2048, 256>>>(Wkv, Wkvb);
    cvt_bf16 <<<1024, 256>>>(Wfc, Wfcb);
    concat_h <<<4096, 256>>>(x, mem);
    fill_pos <<<4096, 256>>>(pos);
    zero_a2row<<<4, 256>>>();

    // G0: q = x@Wq^T -> A2 (q+u | shifted q+v)
    gemm_bf16<0, 64><<<dim3(16, 16, 1), 256, SM64>>>(
        h, Wqb, 1024, 0, 0, u, v, A2, nullptr);
    // G1: kv = h@Wkv^T -> B2 k-half + Vt (R12 champion config)
    gemm_bf16<1, 128><<<dim3(16, 32, 1), 256, SM128>>>(
        h, Wkvb, 1024, 0, 0, nullptr, nullptr, B2, Vt);
    // G2: persistent-column scores -> P = exp(S) + fused Z partials
    g2_scores<<<dim3(8, 32), 256, SMG2>>>(A2, B2, Sp, Zpp);
    // RZ = 1 / sum_y Zp ; fold into Vt
    zinv  <<<256, 256>>>();
    vscale<<<2048, 256>>>();
    // G3: out = P @ Vt^T (pure bf16 GEMM)
    gemm_bf16<3, 64><<<dim3(1, 8, 32), 256, SM64>>>(
        Sp, Vt, 2048, (size_t)1024 * 2048, (size_t)64 * 2048,
        nullptr, nullptr, of, nullptr);
    // G4: y = of@Wfc^T + x + bfc
    gemm_bf16<4, 64><<<dim3(16, 16, 1), 256, SM64>>>(
        of, Wfcb, 1024, 0, 0, x, bfc, y, nullptr);
    // LayerNorm
    ln_kernel<<<2048, 256>>>(gam, bet, out);
}

// round 17
// speedup vs baseline: 1.1947x; 1.0511x over previous
#include <cuda_runtime.h>
#include <cuda_bf16.h>
#include <cstdint>
#include <math.h>
#include <math_constants.h>

// ===========================================================================
// RecurrenceAttention — bf16 mma.sync; 4-stage cp.async GEMMs with prefetch
// distance 2 and single-sync chunk loops; persistent-column scores kernel
// writing P = exp(S) + fused column-Z partials.
//
//  cvt_bf16   : Wq/Wkv/Wfc -> bf16 once
//  concat_h   : h = [mem ; x] bf16
//  fill_pos   : B2 pos half ; zero_a2row
//  G0         : q = x@Wq^T   -> A2 bf16 (q+u | shifted q+v)
//  G1         : kv = h@Wkv^T -> B2 bf16 k-half + Vt bf16 ([bz][d][j])
//  g2_scores  : P = exp(mask(S)*0.125) bf16 + Zp partials
//  zinv/vscale: RZ = 1/sum Zp ; Vt *= RZ
//  G3         : out = P @ Vt^T (pure bf16, masked K-chunks skipped)
//  G4         : y = of@Wfc^T + x + bfc  (fp32 out)
//  ln_kernel  : LayerNorm -> d_out
//
// Sync-elision invariant: with 4 stages and prefetch distance 2, the stage
// written by issue(ch+2) at iteration ch was last READ at iteration ch-2,
// and every warp passed iteration ch-1's __syncthreads() after finishing
// that read — so no trailing stage-release barrier is needed.
// ===========================================================================

// ---------------- scratch ----------------
__device__ __nv_bfloat16 g_h   [4096 * 1024];
__device__ __nv_bfloat16 g_Wqb [1024 * 1024];
__device__ __nv_bfloat16 g_Wkvb[2048 * 1024];
__device__ __nv_bfloat16 g_Wfcb[1024 * 1024];
__device__ __nv_bfloat16 g_A2  [32 * 1024 * 128];
__device__ __nv_bfloat16 g_B2  [32 * 2048 * 128];
__device__ __nv_bfloat16 g_V   [32 * 64 * 2048];       // [bz][d][j]
__device__ __nv_bfloat16 g_S   [32u * 1024u * 2048u];  // holds P = exp(S)
__device__ float g_Zp [8 * 32 * 2048];
__device__ float g_RZ [32 * 2048];
__device__ __nv_bfloat16 g_of  [2048 * 1024];
__device__ float g_y [2048 * 1024];

// ---------------- helpers ----------------
__device__ __forceinline__ uint32_t smem_u32(const void* p) {
    uint32_t a;
    asm("{ .reg .u64 t; cvta.to.shared.u64 t, %1; cvt.u32.u64 %0, t; }"
        : "=r"(a) : "l"(p));
    return a;
}
__device__ __forceinline__ uint32_t pack_bf2(float a, float b) {
    __nv_bfloat162 h = __float22bfloat162_rn(make_float2(a, b));
    return *reinterpret_cast<uint32_t*>(&h);
}
__device__ __forceinline__ void ldsm4(uint32_t* r, uint32_t addr) {
    asm volatile("ldmatrix.sync.aligned.m8n8.x4.shared.b16 {%0,%1,%2,%3}, [%4];"
                 : "=r"(r[0]), "=r"(r[1]), "=r"(r[2]), "=r"(r[3]) : "r"(addr));
}
__device__ __forceinline__ void mma16(float* c, const uint32_t* a,
                                      uint32_t b0, uint32_t b1) {
    asm volatile(
        "mma.sync.aligned.m16n8k16.row.col.f32.bf16.bf16.f32 "
        "{%0,%1,%2,%3}, {%4,%5,%6,%7}, {%8,%9}, {%0,%1,%2,%3};"
        : "+f"(c[0]), "+f"(c[1]), "+f"(c[2]), "+f"(c[3])
        : "r"(a[0]), "r"(a[1]), "r"(a[2]), "r"(a[3]), "r"(b0), "r"(b1));
}
#define CP_ASYNC16(smem, gptr) \
    asm volatile("cp.async.cg.shared.global [%0], [%1], 16;" \
                 :: "r"(smem), "l"(gptr))
#define CP_COMMIT() asm volatile("cp.async.commit_group;" ::: "memory")
template <int N>
__device__ __forceinline__ void cp_wait() {
    asm volatile("cp.async.wait_group %0;" :: "n"(N) : "memory");
}

// fast exp on FMA pipe
__device__ __forceinline__ float fexp(float x) {
    float y = fmaxf(x * 1.4426950408889634f, -126.0f);
    float fn = floorf(y);
    float f  = y - fn;
    float p  = 1.5403530e-4f;
    p = fmaf(p, f, 1.3333558e-3f);
    p = fmaf(p, f, 9.6181291e-3f);
    p = fmaf(p, f, 5.5504109e-2f);
    p = fmaf(p, f, 2.4022651e-1f);
    p = fmaf(p, f, 6.9314718e-1f);
    p = fmaf(p, f, 1.0f);
    return p * __int_as_float(((int)fn + 127) << 23);
}

// ---------------- small kernels ----------------
__global__ __launch_bounds__(256) void cvt_bf16(const float* __restrict__ src,
                                                __nv_bfloat16* __restrict__ dst) {
    size_t i = (size_t)blockIdx.x * 256 + threadIdx.x;
    float4 v = reinterpret_cast<const float4*>(src)[i];
    uint2 o;
    o.x = pack_bf2(v.x, v.y);
    o.y = pack_bf2(v.z, v.w);
    *reinterpret_cast<uint2*>(dst + i * 4) = o;
}

__global__ __launch_bounds__(256) void concat_h(const float* __restrict__ x,
                                                const float* __restrict__ mem) {
    size_t idx = (size_t)blockIdx.x * 256 + threadIdx.x;
    size_t r   = idx >> 8;
    int    c4  = (int)(idx & 255);
    int beta = (int)(r >> 11);
    int s    = (int)(r & 2047);
    const float* src = (s < 1024)
        ? mem + ((size_t)(beta * 1024 + s)) * 1024
        : x   + ((size_t)(beta * 1024 + s - 1024)) * 1024;
    float4 v = reinterpret_cast<const float4*>(src)[c4];
    uint2 o;
    o.x = pack_bf2(v.x, v.y);
    o.y = pack_bf2(v.z, v.w);
    *reinterpret_cast<uint2*>(g_h + idx * 4) = o;
}

__global__ __launch_bounds__(256) void fill_pos(const float* __restrict__ pos_emb) {
    int idx = blockIdx.x * 256 + threadIdx.x;
    int d4 = idx & 15;
    int j  = (idx >> 4) & 2047;
    int bz = idx >> 15;
    int hh = bz & 15;
    float4 p = *reinterpret_cast<const float4*>(pos_emb + (size_t)j * 1024 + hh * 64 + d4 * 4);
    uint2 o;
    o.x = pack_bf2(p.x, p.y);
    o.y = pack_bf2(p.z, p.w);
    *reinterpret_cast<uint2*>(g_B2 + (((size_t)bz * 2048 + j) * 128) + 64 + d4 * 4) = o;
}

__global__ __launch_bounds__(256) void zero_a2row() {
    int t = blockIdx.x * 256 + threadIdx.x;
    int hh = t >> 6, d = t & 63;
    g_A2[(((size_t)hh) * 1024 + 1023) * 128 + 64 + d] = __float2bfloat16(0.0f);
}

// ---------------------------------------------------------------------------
// bf16 GEMM, 4-stage cp.async ring, prefetch distance 2, ONE sync per chunk.
// D(M x N) = A(M x K) * B(N x K)^T, bf16 K-major. BM=128, BN=128/64, BK=32.
// 256 threads, 8 warps 4x2, warp tile 32 x BN/2. 80B-padded rows.
// MODE: 0=qproj(A rows remapped in g_h)  1=kvproj  3=P@V  4=fc
// ---------------------------------------------------------------------------
template <int MODE, int BN>
__global__ __launch_bounds__(256, 2)
void gemm_bf16(const __nv_bfloat16* __restrict__ Ag,
               const __nv_bfloat16* __restrict__ Bg, int K,
               size_t batchA, size_t batchB,
               const float* __restrict__ aux0, const float* __restrict__ aux1,
               void* __restrict__ D0v, void* __restrict__ D1v) {
    constexpr int WN    = BN / 2;
    constexpr int NT    = WN / 8;
    constexpr int NG    = WN / 16;
    constexpr int BPASS = BN / 64;
    constexpr int LOG2BN = (BN == 64) ? 6 : 7;
    constexpr int STAGE  = (128 + BN) * 80;     // bytes per stage (A then B)

    extern __shared__ __align__(16) uint8_t dsm[];

    const int t    = threadIdx.x;
    const int wid  = t >> 5;
    const int lane = t & 31;
    const int wm   = wid >> 1;
    const int wn   = wid & 1;
    const int group = lane >> 2;
    const int tid4  = lane & 3;
    const int rowBase = blockIdx.y * 128;
    const int colBase = blockIdx.x * BN;

    const __nv_bfloat16* A = Ag + (size_t)blockIdx.z * batchA;
    const __nv_bfloat16* B = Bg + (size_t)blockIdx.z * batchB;

    int nch = K >> 5;
    if (MODE == 3) {
        int lim = ((rowBase + 1151) >> 5) + 1;   // skip fully-masked K-chunks
        if (lim < nch) nch = lim;
    }

    float acc[2][NT][4];
#pragma unroll
    for (int mt = 0; mt < 2; mt++)
#pragma unroll
        for (int nt = 0; nt < NT; nt++)
#pragma unroll
            for (int e = 0; e < 4; e++) acc[mt][nt][e] = 0.0f;

    const uint32_t dS = smem_u32(dsm);

    auto issue = [&](int ch) {
        const int kg0 = ch << 5;
        const uint32_t base = dS + (ch & 3) * STAGE;
#pragma unroll
        for (int p = 0; p < 2; p++) {
            int idx = p * 256 + t;
            int r = idx & 127, c = idx >> 7;
            int gr = rowBase + r;
            size_t arow = (MODE == 0)
                ? (size_t)(gr + 1024 + ((gr >> 10) << 10))   // x rows inside g_h
                : (size_t)gr;
            CP_ASYNC16(base + r * 80 + c * 16, A + arow * K + kg0 + c * 8);
        }
#pragma unroll
        for (int p = 0; p < BPASS; p++) {
            int idx = p * 256 + t;
            int r = idx & (BN - 1), c = idx >> LOG2BN;
            CP_ASYNC16(base + 128 * 80 + r * 80 + c * 16,
                       B + (size_t)(colBase + r) * K + kg0 + c * 8);
        }
        CP_COMMIT();
    };

    // prologue: distance 2
    for (int s = 0; s < 2 && s < nch; s++) issue(s);

    const int lrow = (lane & 15) * 80;
    const int kh   = ((lane >> 4) & 1) * 16;

    for (int ch = 0; ch < nch; ch++) {
        if (ch + 2 < nch) issue(ch + 2);   // stage read at ch-2; safe (see top)

        int lag = nch - ch - 1;
        if (lag >= 2)      cp_wait<2>();
        else if (lag == 1) cp_wait<1>();
        else               cp_wait<0>();
        __syncthreads();

        const uint32_t aBase = dS + (ch & 3) * STAGE;
        const uint32_t bBase = aBase + 128 * 80;
#pragma unroll
        for (int ks = 0; ks < 2; ks++) {
            const int kb = ks * 32 + kh;
            uint32_t a[2][4];
#pragma unroll
            for (int mt = 0; mt < 2; mt++)
                ldsm4(a[mt], aBase + (wm * 32 + mt * 16) * 80 + lrow + kb);
            uint32_t bfr[NG][4];
#pragma unroll
            for (int g = 0; g < NG; g++)
                ldsm4(bfr[g], bBase + (wn * WN + g * 16) * 80 + lrow + kb);
#pragma unroll
            for (int mt = 0; mt < 2; mt++)
#pragma unroll
                for (int g = 0; g < NG; g++) {
                    mma16(acc[mt][2 * g],     a[mt], bfr[g][0], bfr[g][2]);
                    mma16(acc[mt][2 * g + 1], a[mt], bfr[g][1], bfr[g][3]);
                }
        }
        // no trailing sync: next overwrite of this stage is 2 iterations away
    }

    // ---- epilogue ----
    auto emit = [&](int gr, int gc, float v0, float v1) {
        if (MODE == 0) {
            __nv_bfloat16* A2p = (__nv_bfloat16*)D0v;
            float2 u2 = *reinterpret_cast<const float2*>(aux0 + gc);
            float2 w2 = *reinterpret_cast<const float2*>(aux1 + gc);
            int betaB = gr >> 10, iq = gr & 1023;
            int hh = gc >> 6, d = gc & 63;
            size_t base = ((size_t)(betaB * 16 + hh) * 1024 + iq) * 128 + d;
            uint32_t q  = pack_bf2(v0 + u2.x, v1 + u2.y);
            uint32_t pv = pack_bf2(v0 + w2.x, v1 + w2.y);
            *reinterpret_cast<uint32_t*>(A2p + base) = q;
            if (betaB == 1)
                *reinterpret_cast<uint32_t*>(A2p + base + 64) = pv;
            else if (iq >= 1)
                *reinterpret_cast<uint32_t*>(A2p + base - 64) = pv;
        } else if (MODE == 1) {
            int betaB = gr >> 11, jj = gr & 2047;
            if (gc < 1024) {
                __nv_bfloat16* B2p = (__nv_bfloat16*)D0v;
                int hh = gc >> 6, d = gc & 63;
                *reinterpret_cast<uint32_t*>(
                    B2p + ((size_t)(betaB * 16 + hh) * 2048 + jj) * 128 + d) =
                    pack_bf2(v0, v1);
            } else {
                __nv_bfloat16* Vp = (__nv_bfloat16*)D1v;
                int c = gc - 1024;
                int hh = c >> 6, d = c & 63;
                size_t base = ((size_t)(betaB * 16 + hh) * 64 + d) * 2048 + jj;
                Vp[base]        = __float2bfloat16(v0);
                Vp[base + 2048] = __float2bfloat16(v1);
            }
        } else if (MODE == 3) {
            __nv_bfloat16* Op = (__nv_bfloat16*)D0v;
            int bz = blockIdx.z, beta = bz >> 4, hh = bz & 15;
            *reinterpret_cast<uint32_t*>(
                Op + ((size_t)(beta * 1024 + gr)) * 1024 + hh * 64 + gc) =
                pack_bf2(v0, v1);
        } else {
            float* Yp = (float*)D0v;
            float2 xv = *reinterpret_cast<const float2*>(aux0 + (size_t)gr * 1024 + gc);
            float2 bv = *reinterpret_cast<const float2*>(aux1 + gc);
            *reinterpret_cast<float2*>(Yp + (size_t)gr * 1024 + gc) =
                make_float2(v0 + xv.x + bv.x, v1 + xv.y + bv.y);
        }
    };

#pragma unroll
    for (int mt = 0; mt < 2; mt++) {
#pragma unroll
        for (int nt = 0; nt < NT; nt++) {
            int gr0 = rowBase + wm * 32 + mt * 16 + group;
            int gc  = colBase + wn * WN + nt * 8 + tid4 * 2;
            emit(gr0,     gc, acc[mt][nt][0], acc[mt][nt][1]);
            emit(gr0 + 8, gc, acc[mt][nt][2], acc[mt][nt][3]);
        }
    }
}

// ---------------------------------------------------------------------------
// Persistent-column scores kernel. 4-stage cp.async B ring over the flattened
// (tile, chunk) stream, prefetch distance 2, ONE sync per chunk.
// Writes P = exp(mask(S)*0.125) bf16 and column Z partials.
// grid (8 rowblocks, 32 bz).
// ---------------------------------------------------------------------------
__global__ __launch_bounds__(256, 2)
void g2_scores(const __nv_bfloat16* __restrict__ A2g,
               const __nv_bfloat16* __restrict__ B2g,
               __nv_bfloat16* __restrict__ Sp, float* __restrict__ Zp) {
    extern __shared__ __align__(16) uint8_t dsm[];
    uint8_t* sA  = dsm;                       // 4 chunks x 128 x 80 = 40960
    uint8_t* sB  = dsm + 40960;               // 4-stage ring x 10240 = 40960
    float*   sZw = (float*)(dsm + 81920);     // 4 x 128 floats

    const int t    = threadIdx.x;
    const int wid  = t >> 5;
    const int lane = t & 31;
    const int wm   = wid >> 1;
    const int wn   = wid & 1;
    const int group = lane >> 2;
    const int tid4  = lane & 3;
    const int y  = blockIdx.x;
    const int z  = blockIdx.y;
    const int rowBase = y * 128;

    const __nv_bfloat16* A = A2g + (size_t)z * 1024 * 128;
    const __nv_bfloat16* B = B2g + (size_t)z * 2048 * 128;
    __nv_bfloat16* Srow = Sp + (size_t)z * 1024 * 2048;
    float* Zrow = Zp + ((size_t)(y * 32) + z) * 2048;

#pragma unroll
    for (int ck = 0; ck < 4; ck++)
#pragma unroll
        for (int p = 0; p < 2; p++) {
            int idx = p * 256 + t;
            int r = idx & 127, c = idx >> 7;
            *reinterpret_cast<uint4*>(&sA[ck * 10240 + r * 80 + c * 16]) =
                *reinterpret_cast<const uint4*>(
                    A + (size_t)(rowBase + r) * 128 + ck * 32 + c * 8);
        }

    const int nvt = min(16, y + 9);
    const int totalc = nvt * 4;
    const int lrow = (lane & 15) * 80;
    const int kh   = ((lane >> 4) & 1) * 16;
    const uint32_t aS = smem_u32(sA);
    const uint32_t bS = smem_u32(sB);

    auto issueB = [&](int fc) {
        const __nv_bfloat16* Bt = B + (size_t)(fc >> 2) * 16384 + (fc & 3) * 32;
        const uint32_t base = bS + (fc & 3) * 10240;
#pragma unroll
        for (int p = 0; p < 2; p++) {
            int idx = p * 256 + t;
            int r = idx & 127, c = idx >> 7;
            CP_ASYNC16(base + r * 80 + c * 16, Bt + (size_t)r * 128 + c * 8);
        }
        CP_COMMIT();
    };

    for (int s = 0; s < 2 && s < totalc; s++) issueB(s);
    __syncthreads();                           // A strip visible to all warps

    int fc = 0;
    for (int ct = 0; ct < nvt; ct++) {
        float acc[2][8][4];
#pragma unroll
        for (int mt = 0; mt < 2; mt++)
#pragma unroll
            for (int nt = 0; nt < 8; nt++)
#pragma unroll
                for (int e = 0; e < 4; e++) acc[mt][nt][e] = 0.0f;

#pragma unroll
        for (int ck = 0; ck < 4; ck++, fc++) {
            if (fc + 2 < totalc) issueB(fc + 2);

            int lag = totalc - fc - 1;
            if (lag >= 2)      cp_wait<2>();
            else if (lag == 1) cp_wait<1>();
            else               cp_wait<0>();
            __syncthreads();

            uint32_t aBase = aS + ck * 10240;
            uint32_t bBase = bS + (fc & 3) * 10240;
#pragma unroll
            for (int ks = 0; ks < 2; ks++) {
                const int kb = ks * 32 + kh;
                uint32_t a[2][4];
#pragma unroll
                for (int mt = 0; mt < 2; mt++)
                    ldsm4(a[mt], aBase + (wm * 32 + mt * 16) * 80 + lrow + kb);
                uint32_t bfr[4][4];
#pragma unroll
                for (int g = 0; g < 4; g++)
                    ldsm4(bfr[g], bBase + (wn * 64 + g * 16) * 80 + lrow + kb);
#pragma unroll
                for (int mt = 0; mt < 2; mt++)
#pragma unroll
                    for (int g = 0; g < 4; g++) {
                        mma16(acc[mt][2 * g],     a[mt], bfr[g][0], bfr[g][2]);
                        mma16(acc[mt][2 * g + 1], a[mt], bfr[g][1], bfr[g][3]);
                    }
            }
            // no trailing sync (distance-2 invariant)
        }

        const int colBase = ct * 128;
        float colsum[8][2];
#pragma unroll
        for (int nt = 0; nt < 8; nt++) { colsum[nt][0] = 0.0f; colsum[nt][1] = 0.0f; }

#pragma unroll
        for (int mt = 0; mt < 2; mt++) {
#pragma unroll
            for (int nt = 0; nt < 8; nt++) {
                int gr0 = rowBase + wm * 32 + mt * 16 + group;
                int gc  = colBase + wn * 64 + nt * 8 + tid4 * 2;
                int gr1 = gr0 + 8;
                float e0 = (gc + 0 > gr0 + 1024) ? 0.0f : fexp(acc[mt][nt][0] * 0.125f);
                float e1 = (gc + 1 > gr0 + 1024) ? 0.0f : fexp(acc[mt][nt][1] * 0.125f);
                float e2 = (gc + 0 > gr1 + 1024) ? 0.0f : fexp(acc[mt][nt][2] * 0.125f);
                float e3 = (gc + 1 > gr1 + 1024) ? 0.0f : fexp(acc[mt][nt][3] * 0.125f);
                uint32_t pk0 = pack_bf2(e0, e1);
                uint32_t pk1 = pack_bf2(e2, e3);
                *reinterpret_cast<uint32_t*>(Srow + (size_t)gr0 * 2048 + gc) = pk0;
                *reinterpret_cast<uint32_t*>(Srow + (size_t)gr1 * 2048 + gc) = pk1;
                float2 f0 = __bfloat1622float2(*reinterpret_cast<__nv_bfloat162*>(&pk0));
                float2 f1 = __bfloat1622float2(*reinterpret_cast<__nv_bfloat162*>(&pk1));
                colsum[nt][0] += f0.x + f1.x;
                colsum[nt][1] += f0.y + f1.y;
            }
        }

        // epilogue Z-reduction needs its own barrier pair around sZw reuse
        __syncthreads();
#pragma unroll
        for (int nt = 0; nt < 8; nt++)
#pragma unroll
            for (int e = 0; e < 2; e++) {
                float v = colsum[nt][e];
                v += __shfl_xor_sync(0xFFFFFFFFu, v, 4);
                v += __shfl_xor_sync(0xFFFFFFFFu, v, 8);
                v += __shfl_xor_sync(0xFFFFFFFFu, v, 16);
                if (lane < 4)
                    sZw[wm * 128 + wn * 64 + nt * 8 + lane * 2 + e] = v;
            }
        __syncthreads();
        if (t < 128) {
            float zs = sZw[t] + sZw[128 + t] + sZw[256 + t] + sZw[384 + t];
            Zrow[colBase + t] = zs;
        }
    }

    for (int ct = nvt; ct < 16; ct++)
        if (t < 128) Zrow[ct * 128 + t] = 0.0f;
}

// RZ[bz][j] = 1 / sum_y Zp[y][bz][j]
__global__ __launch_bounds__(256) void zinv() {
    int idx = blockIdx.x * 256 + threadIdx.x;
    int bz = idx >> 11, j = idx & 2047;
    float s = 0.0f;
#pragma unroll
    for (int y = 0; y < 8; y++)
        s += g_Zp[((size_t)(y * 32) + bz) * 2048 + j];
    g_RZ[bz * 2048 + j] = 1.0f / s;
}

// Vt[bz][d][j] *= RZ[bz][j]  (8 bf16 per thread)
__global__ __launch_bounds__(256) void vscale() {
    int i = blockIdx.x * 256 + threadIdx.x;
    int j8 = (i & 255) * 8;
    int bz = i >> 14;
    __nv_bfloat16* vp = g_V + ((size_t)(i >> 8)) * 2048 + j8;
    const float* rz = g_RZ + bz * 2048 + j8;
    uint4 o = *reinterpret_cast<const uint4*>(vp);
    float4 r0 = *reinterpret_cast<const float4*>(rz);
    float4 r1 = *reinterpret_cast<const float4*>(rz + 4);
    __nv_bfloat162* hp = reinterpret_cast<__nv_bfloat162*>(&o);
    float2 p0 = __bfloat1622float2(hp[0]);
    float2 p1 = __bfloat1622float2(hp[1]);
    float2 p2 = __bfloat1622float2(hp[2]);
    float2 p3 = __bfloat1622float2(hp[3]);
    o.x = pack_bf2(p0.x * r0.x, p0.y * r0.y);
    o.y = pack_bf2(p1.x * r0.z, p1.y * r0.w);
    o.z = pack_bf2(p2.x * r1.x, p2.y * r1.y);
    o.w = pack_bf2(p3.x * r1.z, p3.y * r1.w);
    *reinterpret_cast<uint4*>(vp) = o;
}

// ---------------------------------------------------------------------------
__global__ __launch_bounds__(256) void ln_kernel(const float* __restrict__ gamma,
                                                 const float* __restrict__ beta,
                                                 float* __restrict__ out) {
    int row = blockIdx.x;
    const float4* yr = reinterpret_cast<const float4*>(g_y + (size_t)row * 1024);
    int t = threadIdx.x;
    float4 v = yr[t];
    float s  = v.x + v.y + v.z + v.w;
    float s2 = v.x * v.x + v.y * v.y + v.z * v.z + v.w * v.w;
#pragma unroll
    for (int off = 16; off; off >>= 1) {
        s  += __shfl_xor_sync(0xFFFFFFFFu, s,  off);
        s2 += __shfl_xor_sync(0xFFFFFFFFu, s2, off);
    }
    __shared__ float shs[8], shs2[8];
    int w = t >> 5, lane = t & 31;
    if (lane == 0) { shs[w] = s; shs2[w] = s2; }
    __syncthreads();
    float ts = 0.0f, ts2 = 0.0f;
#pragma unroll
    for (int i = 0; i < 8; i++) { ts += shs[i]; ts2 += shs2[i]; }
    float mu   = ts * (1.0f / 1024.0f);
    float var  = ts2 * (1.0f / 1024.0f) - mu * mu;
    float rstd = rsqrtf(var + 1e-5f);

    float4 g = reinterpret_cast<const float4*>(gamma)[t];
    float4 b = reinterpret_cast<const float4*>(beta)[t];
    float4 o;
    o.x = (v.x - mu) * rstd * g.x + b.x;
    o.y = (v.y - mu) * rstd * g.y + b.y;
    o.z = (v.z - mu) * rstd * g.z + b.z;
    o.w = (v.w - mu) * rstd * g.w + b.w;
    reinterpret_cast<float4*>(out + (size_t)row * 1024)[t] = o;
}

// ---------------------------------------------------------------------------
extern "C" void kernel_launch(void* const* d_in, const int* in_sizes, int n_in,
                              void* d_out, int out_size) {
    const float* x    = (const float*)d_in[0];
    const float* pos  = (const float*)d_in[1];
    const float* u    = (const float*)d_in[2];
    const float* v    = (const float*)d_in[3];
    const float* mem  = (const float*)d_in[4];
    const float* Wq   = (const float*)d_in[6];
    const float* Wkv  = (const float*)d_in[7];
    const float* Wfc  = (const float*)d_in[8];
    const float* bfc  = (const float*)d_in[9];
    const float* gam  = (const float*)d_in[10];
    const float* bet  = (const float*)d_in[11];
    float* out = (float*)d_out;

    __nv_bfloat16 *A2, *B2, *Vt, *h, *of, *Sp, *Wqb, *Wkvb, *Wfcb;
    float *y, *Zpp;
    cudaGetSymbolAddress((void**)&h,    g_h);
    cudaGetSymbolAddress((void**)&Wqb,  g_Wqb);
    cudaGetSymbolAddress((void**)&Wkvb, g_Wkvb);
    cudaGetSymbolAddress((void**)&Wfcb, g_Wfcb);
    cudaGetSymbolAddress((void**)&A2,   g_A2);
    cudaGetSymbolAddress((void**)&B2,   g_B2);
    cudaGetSymbolAddress((void**)&Vt,   g_V);
    cudaGetSymbolAddress((void**)&of,   g_of);
    cudaGetSymbolAddress((void**)&y,    g_y);
    cudaGetSymbolAddress((void**)&Sp,   g_S);
    cudaGetSymbolAddress((void**)&Zpp,  g_Zp);

    constexpr int SM64  = 4 * (128 + 64) * 80;    // 61440
    constexpr int SM128 = 4 * (128 + 128) * 80;   // 81920
    constexpr int SMG2  = 81920 + 2048;           // 83968
    static bool attr_done = false;
    if (!attr_done) {
        cudaFuncSetAttribute(g2_scores,
                             cudaFuncAttributeMaxDynamicSharedMemorySize, SMG2);
        cudaFuncSetAttribute(gemm_bf16<0, 64>,
                             cudaFuncAttributeMaxDynamicSharedMemorySize, SM64);
        cudaFuncSetAttribute(gemm_bf16<1, 128>,
                             cudaFuncAttributeMaxDynamicSharedMemorySize, SM128);
        cudaFuncSetAttribute(gemm_bf16<3, 64>,
                             cudaFuncAttributeMaxDynamicSharedMemorySize, SM64);
        cudaFuncSetAttribute(gemm_bf16<4, 64>,
                             cudaFuncAttributeMaxDynamicSharedMemorySize, SM64);
        attr_done = true;
    }

    cvt_bf16 <<<1024, 256>>>(Wq,  Wqb);
    cvt_bf16 <<<2048, 256>>>(Wkv, Wkvb);
    cvt_bf16 <<<1024, 256>>>(Wfc, Wfcb);
    concat_h <<<4096, 256>>>(x, mem);
    fill_pos <<<4096, 256>>>(pos);
    zero_a2row<<<4, 256>>>();

    // G0: q = x@Wq^T -> A2 (q+u | shifted q+v)
    gemm_bf16<0, 64><<<dim3(16, 16, 1), 256, SM64>>>(
        h, Wqb, 1024, 0, 0, u, v, A2, nullptr);
    // G1: kv = h@Wkv^T -> B2 k-half + Vt
    gemm_bf16<1, 128><<<dim3(16, 32, 1), 256, SM128>>>(
        h, Wkvb, 1024, 0, 0, nullptr, nullptr, B2, Vt);
    // G2: persistent-column scores -> P = exp(S) + fused Z partials
    g2_scores<<<dim3(8, 32), 256, SMG2>>>(A2, B2, Sp, Zpp);
    // RZ = 1 / sum_y Zp ; fold into Vt
    zinv  <<<256, 256>>>();
    vscale<<<2048, 256>>>();
    // G3: out = P @ Vt^T (pure bf16 GEMM)
    gemm_bf16<3, 64><<<dim3(1, 8, 32), 256, SM64>>>(
        Sp, Vt, 2048, (size_t)1024 * 2048, (size_t)64 * 2048,
        nullptr, nullptr, of, nullptr);
    // G4: y = of@Wfc^T + x + bfc
    gemm_bf16<4, 64><<<dim3(16, 16, 1), 256, SM64>>>(
        of, Wfcb, 1024, 0, 0, x, bfc, y, nullptr);
    // LayerNorm
    ln_kernel<<<2048, 256>>>(gam, bet, out);
}